// round 1
// baseline (speedup 1.0000x reference)
#include <cuda_runtime.h>
#include <math_constants.h>

// Problem constants
#define BATCH   4
#define T_SEQ   2048
#define CDIM    384
#define HEADS   6
#define DH      64
#define MROWS   (BATCH * T_SEQ)        // 8192

// ---------------- scratch (static device globals; no runtime allocation) ----
__device__ float g_q[BATCH * HEADS * T_SEQ * DH];   // [B,H,T,D]
__device__ float g_k[BATCH * HEADS * T_SEQ * DH];
__device__ float g_v[BATCH * HEADS * T_SEQ * DH];
__device__ float g_ctx[MROWS * CDIM];               // [B*T, C]

// ---------------- generic tiled fp32 GEMM: out = A[M,K] @ W[K,N] + bias -----
// BM=BN=64, BK=16, 256 threads, 4x4 register microtile per thread.
// bhtd == 0 : out is row-major [M,N]
// bhtd == 1 : out[((b*H+h)*T + t)*DH + d]  with m=(b,t), n=(h,d)
__global__ __launch_bounds__(256) void gemm_bias_kernel(
    const float* __restrict__ A, const float* __restrict__ W,
    const float* __restrict__ bias, float* __restrict__ out,
    int M, int N, int K, int bhtd)
{
    __shared__ float As[16][64];   // [k][m]
    __shared__ float Ws[16][64];   // [k][n]

    const int tid = threadIdx.x;
    const int n0 = blockIdx.x * 64;
    const int m0 = blockIdx.y * 64;

    const int ty = tid >> 4;       // 0..15 -> row group
    const int tx = tid & 15;       // 0..15 -> col group

    float acc[4][4];
#pragma unroll
    for (int i = 0; i < 4; i++)
#pragma unroll
        for (int j = 0; j < 4; j++) acc[i][j] = 0.f;

    // loader indices
    const int ar = tid >> 2;           // 0..63 A row within tile
    const int ac4 = tid & 3;           // 0..3  A float4 col
    const int wr = tid >> 4;           // 0..15 W row (k)
    const int wc4 = tid & 15;          // 0..15 W float4 col

    for (int k0 = 0; k0 < K; k0 += 16) {
        // load A tile (64x16) transposed into As[k][m]
        float4 a = *reinterpret_cast<const float4*>(&A[(size_t)(m0 + ar) * K + k0 + ac4 * 4]);
        As[ac4 * 4 + 0][ar] = a.x;
        As[ac4 * 4 + 1][ar] = a.y;
        As[ac4 * 4 + 2][ar] = a.z;
        As[ac4 * 4 + 3][ar] = a.w;
        // load W tile (16x64)
        float4 w = *reinterpret_cast<const float4*>(&W[(size_t)(k0 + wr) * N + n0 + wc4 * 4]);
        *reinterpret_cast<float4*>(&Ws[wr][wc4 * 4]) = w;
        __syncthreads();

#pragma unroll
        for (int kk = 0; kk < 16; kk++) {
            float4 av = *reinterpret_cast<const float4*>(&As[kk][ty * 4]);
            float4 bv = *reinterpret_cast<const float4*>(&Ws[kk][tx * 4]);
            float ar4[4] = {av.x, av.y, av.z, av.w};
            float br4[4] = {bv.x, bv.y, bv.z, bv.w};
#pragma unroll
            for (int i = 0; i < 4; i++)
#pragma unroll
                for (int j = 0; j < 4; j++) acc[i][j] += ar4[i] * br4[j];
        }
        __syncthreads();
    }

    // epilogue
#pragma unroll
    for (int i = 0; i < 4; i++) {
        const int m = m0 + ty * 4 + i;
#pragma unroll
        for (int j = 0; j < 4; j++) {
            const int n = n0 + tx * 4 + j;
            const float val = acc[i][j] + bias[n];
            if (bhtd) {
                const int b = m / T_SEQ, t = m % T_SEQ;
                const int h = n / DH,   d = n % DH;
                out[((size_t)(b * HEADS + h) * T_SEQ + t) * DH + d] = val;
            } else {
                out[(size_t)m * N + n] = val;
            }
        }
    }
}

// ---------------- causal flash attention (fp32) ----------------------------
// grid: (T/BQ, B*H); 256 threads. BQ=32 queries, BKT=32 key tile.
#define BQ  32
#define BKT 32

__global__ __launch_bounds__(256) void attn_kernel(float* __restrict__ ctx)
{
    __shared__ float Qs[BQ][DH];
    __shared__ float Ks[BKT][DH];
    __shared__ float Vs[BKT][DH];
    __shared__ float Ss[BQ][BKT + 1];
    __shared__ float m_s[BQ], l_s[BQ], alpha_s[BQ];

    const int bh  = blockIdx.y;           // b*H + h
    const int q0  = blockIdx.x * BQ;
    const int tid = threadIdx.x;

    const float* qb = g_q + (size_t)bh * T_SEQ * DH;
    const float* kb = g_k + (size_t)bh * T_SEQ * DH;
    const float* vb = g_v + (size_t)bh * T_SEQ * DH;

    // load Q tile, pre-scaled by 1/sqrt(64)
    for (int i = tid; i < BQ * DH; i += 256)
        Qs[i / DH][i % DH] = qb[(size_t)(q0 + i / DH) * DH + (i % DH)] * 0.125f;
    if (tid < BQ) { m_s[tid] = -CUDART_INF_F; l_s[tid] = 0.f; }

    float acc[8];
#pragma unroll
    for (int j = 0; j < 8; j++) acc[j] = 0.f;
    const int q  = tid >> 3;               // 0..31 query row owned
    const int d0 = (tid & 7) * 8;          // 8 output dims owned

    const int ntiles = blockIdx.x + 1;     // causal: only tiles <= diagonal
    for (int kt = 0; kt < ntiles; kt++) {
        const int k0 = kt * BKT;
        __syncthreads();
        for (int i = tid; i < BKT * DH; i += 256) {
            const int r = i / DH, c = i % DH;
            Ks[r][c] = kb[(size_t)(k0 + r) * DH + c];
            Vs[r][c] = vb[(size_t)(k0 + r) * DH + c];
        }
        __syncthreads();

        const bool diag = (kt == blockIdx.x);
#pragma unroll
        for (int s = 0; s < 4; s++) {
            const int idx = tid + s * 256;     // 0..1023
            const int qq = idx >> 5;
            const int kk = idx & 31;
            float sum = 0.f;
#pragma unroll
            for (int dd = 0; dd < DH; dd++) sum += Qs[qq][dd] * Ks[kk][dd];
            if (diag && kk > qq) sum = -CUDART_INF_F;
            Ss[qq][kk] = sum;
        }
        __syncthreads();

        if (tid < BQ) {
            const float mo = m_s[tid];
            float mx = mo;
#pragma unroll 8
            for (int kk = 0; kk < BKT; kk++) mx = fmaxf(mx, Ss[tid][kk]);
            float sum = 0.f;
#pragma unroll 8
            for (int kk = 0; kk < BKT; kk++) {
                const float p = __expf(Ss[tid][kk] - mx);
                Ss[tid][kk] = p;
                sum += p;
            }
            const float alpha = (mo == -CUDART_INF_F) ? 0.f : __expf(mo - mx);
            l_s[tid] = l_s[tid] * alpha + sum;
            m_s[tid] = mx;
            alpha_s[tid] = alpha;
        }
        __syncthreads();

        const float alpha = alpha_s[q];
#pragma unroll
        for (int j = 0; j < 8; j++) acc[j] *= alpha;
#pragma unroll 4
        for (int kk = 0; kk < BKT; kk++) {
            const float p = Ss[q][kk];
#pragma unroll
            for (int j = 0; j < 8; j++) acc[j] += p * Vs[kk][d0 + j];
        }
    }

    const float inv = 1.f / l_s[q];
    const int b = bh / HEADS, h = bh % HEADS;
    float* o = ctx + (size_t)(b * T_SEQ + q0 + q) * CDIM + h * DH + d0;
#pragma unroll
    for (int j = 0; j < 8; j++) o[j] = acc[j] * inv;
}

// ---------------- launch ----------------------------------------------------
extern "C" void kernel_launch(void* const* d_in, const int* in_sizes, int n_in,
                              void* d_out, int out_size)
{
    (void)in_sizes; (void)n_in; (void)out_size;
    const float* x  = (const float*)d_in[0];
    const float* Wq = (const float*)d_in[1];
    const float* bq = (const float*)d_in[2];
    const float* Wk = (const float*)d_in[3];
    const float* bk = (const float*)d_in[4];
    const float* Wv = (const float*)d_in[5];
    const float* bv = (const float*)d_in[6];
    const float* Wo = (const float*)d_in[7];
    const float* bo = (const float*)d_in[8];
    float* out = (float*)d_out;

    static float *qp = nullptr, *kp = nullptr, *vp = nullptr, *cp = nullptr;
    if (!qp) {
        cudaGetSymbolAddress((void**)&qp, g_q);
        cudaGetSymbolAddress((void**)&kp, g_k);
        cudaGetSymbolAddress((void**)&vp, g_v);
        cudaGetSymbolAddress((void**)&cp, g_ctx);
    }

    dim3 gblk(256);
    dim3 ggrid(CDIM / 64, MROWS / 64);   // (6, 128)

    // QKV projections -> [B,H,T,D] scratch
    gemm_bias_kernel<<<ggrid, gblk>>>(x, Wq, bq, qp, MROWS, CDIM, CDIM, 1);
    gemm_bias_kernel<<<ggrid, gblk>>>(x, Wk, bk, kp, MROWS, CDIM, CDIM, 1);
    gemm_bias_kernel<<<ggrid, gblk>>>(x, Wv, bv, vp, MROWS, CDIM, CDIM, 1);

    // causal attention -> ctx [B*T, C]
    dim3 agrid(T_SEQ / BQ, BATCH * HEADS);   // (64, 24)
    attn_kernel<<<agrid, 256>>>(cp);

    // output projection -> d_out
    gemm_bias_kernel<<<ggrid, gblk>>>(cp, Wo, bo, out, MROWS, CDIM, CDIM, 0);
}

// round 2
// speedup vs baseline: 3.0933x; 3.0933x over previous
#include <cuda_runtime.h>

// Problem constants
#define BATCH   4
#define T_SEQ   2048
#define CDIM    384
#define HEADS   6
#define DH      64
#define MROWS   (BATCH * T_SEQ)        // 8192

// ---------------- scratch (static device globals; no runtime allocation) ----
__device__ float g_q[BATCH * HEADS * T_SEQ * DH];   // [B,H,T,D]
__device__ float g_k[BATCH * HEADS * T_SEQ * DH];
__device__ float g_v[BATCH * HEADS * T_SEQ * DH];
__device__ float g_ctx[MROWS * CDIM];               // [B*T, C]

// ---------------- tiled fp32 GEMM: out = A[M,K] @ W[K,N] + bias -------------
// 128x128 tile, BK=16, 256 threads, 8x8 split microtile (rows ty*4/+64, cols tx*4/+64)
__global__ __launch_bounds__(256, 2) void gemm_bias_kernel(
    const float* __restrict__ A, const float* __restrict__ W,
    const float* __restrict__ bias, float* __restrict__ out,
    int M, int N, int K, int bhtd)
{
    __shared__ float As[16][132];   // A^T tile: As[k][m], padded
    __shared__ float Ws[16][128];   // W tile:   Ws[k][n]

    const int tid = threadIdx.x;
    const int n0 = blockIdx.x * 128;
    const int m0 = blockIdx.y * 128;
    const int ty = tid >> 4;        // 0..15
    const int tx = tid & 15;        // 0..15

    float acc[8][8];
#pragma unroll
    for (int i = 0; i < 8; i++)
#pragma unroll
        for (int j = 0; j < 8; j++) acc[i][j] = 0.f;

    for (int k0 = 0; k0 < K; k0 += 16) {
        // load A tile: 128 rows x 16 cols = 512 float4, 2 per thread (transpose into As)
#pragma unroll
        for (int p = 0; p < 2; p++) {
            int idx = tid + 256 * p;
            int row = idx >> 2, c4 = idx & 3;
            float4 a = *reinterpret_cast<const float4*>(&A[(size_t)(m0 + row) * K + k0 + c4 * 4]);
            As[c4 * 4 + 0][row] = a.x;
            As[c4 * 4 + 1][row] = a.y;
            As[c4 * 4 + 2][row] = a.z;
            As[c4 * 4 + 3][row] = a.w;
        }
        // load W tile: 16 rows x 128 cols = 512 float4, 2 per thread
#pragma unroll
        for (int p = 0; p < 2; p++) {
            int idx = tid + 256 * p;
            int wr = idx >> 5, wc4 = idx & 31;
            *reinterpret_cast<float4*>(&Ws[wr][wc4 * 4]) =
                *reinterpret_cast<const float4*>(&W[(size_t)(k0 + wr) * N + n0 + wc4 * 4]);
        }
        __syncthreads();

#pragma unroll
        for (int kk = 0; kk < 16; kk++) {
            float4 a0 = *reinterpret_cast<const float4*>(&As[kk][ty * 4]);
            float4 a1 = *reinterpret_cast<const float4*>(&As[kk][ty * 4 + 64]);
            float4 b0 = *reinterpret_cast<const float4*>(&Ws[kk][tx * 4]);
            float4 b1 = *reinterpret_cast<const float4*>(&Ws[kk][tx * 4 + 64]);
            float av[8] = {a0.x, a0.y, a0.z, a0.w, a1.x, a1.y, a1.z, a1.w};
            float bv[8] = {b0.x, b0.y, b0.z, b0.w, b1.x, b1.y, b1.z, b1.w};
#pragma unroll
            for (int i = 0; i < 8; i++)
#pragma unroll
                for (int j = 0; j < 8; j++) acc[i][j] += av[i] * bv[j];
        }
        __syncthreads();
    }

    // epilogue: two float4 stores per row-slot
#pragma unroll
    for (int i = 0; i < 8; i++) {
        const int m = m0 + ty * 4 + ((i < 4) ? i : 60 + i);
#pragma unroll
        for (int jh = 0; jh < 2; jh++) {
            const int n = n0 + tx * 4 + jh * 64;
            float4 v;
            v.x = acc[i][jh * 4 + 0] + bias[n + 0];
            v.y = acc[i][jh * 4 + 1] + bias[n + 1];
            v.z = acc[i][jh * 4 + 2] + bias[n + 2];
            v.w = acc[i][jh * 4 + 3] + bias[n + 3];
            if (bhtd) {
                const int b = m >> 11, t = m & 2047;
                const int h = n >> 6, d = n & 63;
                *reinterpret_cast<float4*>(
                    &out[(((size_t)(b * HEADS + h) * T_SEQ + t) * DH) + d]) = v;
            } else {
                *reinterpret_cast<float4*>(&out[(size_t)m * N + n]) = v;
            }
        }
    }
}

// ---------------- causal flash attention (fp32, register-blocked) -----------
#define BQ  128
#define BK  64
// dynamic smem layout (floats):
#define QS_LD 132
#define KS_LD 68
#define VS_LD 68
#define PS_LD 68
#define QS_OFF 0
#define KS_OFF (QS_OFF + DH * QS_LD)          // 8448
#define VS_OFF (KS_OFF + BK * KS_LD)          // +4352
#define PS_OFF (VS_OFF + BK * VS_LD)          // +4352
#define SMEM_ATTN_FLOATS (PS_OFF + BQ * PS_LD)  // +8704 = 25856
#define SMEM_ATTN_BYTES  (SMEM_ATTN_FLOATS * 4) // 103424

__global__ __launch_bounds__(256, 2) void attn_kernel(float* __restrict__ ctx)
{
    extern __shared__ float sm[];
    float* Qs = sm + QS_OFF;   // [DH][132]  Q^T, pre-scaled
    float* Ks = sm + KS_OFF;   // [DH][68]   K^T
    float* Vs = sm + VS_OFF;   // [BK][68]   V natural
    float* Ps = sm + PS_OFF;   // [BQ][68]   P row-major

    const int bh  = blockIdx.y;
    const int qi  = gridDim.x - 1 - blockIdx.x;   // heavy blocks launch first
    const int q0  = qi * BQ;
    const int tid = threadIdx.x;
    const int ty  = tid >> 4;
    const int tx  = tid & 15;

    const float* qb = g_q + (size_t)bh * T_SEQ * DH;
    const float* kb = g_k + (size_t)bh * T_SEQ * DH;
    const float* vb = g_v + (size_t)bh * T_SEQ * DH;

    // load Q tile transposed + pre-scaled by 1/sqrt(64)
#pragma unroll
    for (int p = 0; p < 32; p++) {
        int idx = tid + 256 * p;
        int d = idx & 63, m = idx >> 6;
        Qs[d * QS_LD + m] = qb[(size_t)(q0 + m) * DH + d] * 0.125f;
    }

    // per-thread row slots: rows ty*4+{0..3} and ty*4+64+{0..3}
    int rrow[8], ro[8];
#pragma unroll
    for (int i = 0; i < 8; i++) {
        rrow[i] = ty * 4 + ((i < 4) ? i : 60 + i);
        ro[i]   = rrow[i] * PS_LD;
    }

    float O[8][4];
#pragma unroll
    for (int i = 0; i < 8; i++)
#pragma unroll
        for (int j = 0; j < 4; j++) O[i][j] = 0.f;
    float mrow[8], lrow[8];
#pragma unroll
    for (int i = 0; i < 8; i++) { mrow[i] = -1e30f; lrow[i] = 0.f; }

    const int ntiles = 2 * qi + 2;   // causal: k tiles covering k <= q0+127
    for (int kt = 0; kt < ntiles; kt++) {
        const int k0 = kt * BK;
        __syncthreads();
        // K transposed (scalar, coalesced gmem; 4-way smem write conflicts tolerated)
#pragma unroll
        for (int p = 0; p < 16; p++) {
            int idx = tid + 256 * p;
            int d = idx & 63, n = idx >> 6;
            Ks[d * KS_LD + n] = kb[(size_t)(k0 + n) * DH + d];
        }
        // V natural, float4
#pragma unroll
        for (int p = 0; p < 4; p++) {
            int idx = tid + 256 * p;
            int n = idx >> 4, c4 = idx & 15;
            *reinterpret_cast<float4*>(&Vs[n * VS_LD + c4 * 4]) =
                *reinterpret_cast<const float4*>(&vb[(size_t)(k0 + n) * DH + c4 * 4]);
        }
        __syncthreads();

        // S = Q K^T : 8x4 register microtile
        float s[8][4];
#pragma unroll
        for (int i = 0; i < 8; i++)
#pragma unroll
            for (int j = 0; j < 4; j++) s[i][j] = 0.f;
#pragma unroll 8
        for (int kk = 0; kk < DH; kk++) {
            float4 a0 = *reinterpret_cast<const float4*>(&Qs[kk * QS_LD + ty * 4]);
            float4 a1 = *reinterpret_cast<const float4*>(&Qs[kk * QS_LD + ty * 4 + 64]);
            float4 b  = *reinterpret_cast<const float4*>(&Ks[kk * KS_LD + tx * 4]);
            float av[8] = {a0.x, a0.y, a0.z, a0.w, a1.x, a1.y, a1.z, a1.w};
#pragma unroll
            for (int i = 0; i < 8; i++) {
                s[i][0] += av[i] * b.x;
                s[i][1] += av[i] * b.y;
                s[i][2] += av[i] * b.z;
                s[i][3] += av[i] * b.w;
            }
        }

        // causal mask (only diagonal-crossing tiles)
        if (k0 + BK - 1 > q0) {
#pragma unroll
            for (int i = 0; i < 8; i++) {
                const int qg = q0 + rrow[i];
#pragma unroll
                for (int j = 0; j < 4; j++)
                    if (k0 + tx * 4 + j > qg) s[i][j] = -1e30f;
            }
        }

        // online softmax: reduce across the 16-lane tx-group via shfl
#pragma unroll
        for (int i = 0; i < 8; i++) {
            float mx = fmaxf(fmaxf(s[i][0], s[i][1]), fmaxf(s[i][2], s[i][3]));
            mx = fmaxf(mx, __shfl_xor_sync(0xffffffffu, mx, 1));
            mx = fmaxf(mx, __shfl_xor_sync(0xffffffffu, mx, 2));
            mx = fmaxf(mx, __shfl_xor_sync(0xffffffffu, mx, 4));
            mx = fmaxf(mx, __shfl_xor_sync(0xffffffffu, mx, 8));
            const float mnew  = fmaxf(mrow[i], mx);
            const float alpha = __expf(mrow[i] - mnew);
            float sum = 0.f;
#pragma unroll
            for (int j = 0; j < 4; j++) {
                s[i][j] = __expf(s[i][j] - mnew);
                sum += s[i][j];
            }
            sum += __shfl_xor_sync(0xffffffffu, sum, 1);
            sum += __shfl_xor_sync(0xffffffffu, sum, 2);
            sum += __shfl_xor_sync(0xffffffffu, sum, 4);
            sum += __shfl_xor_sync(0xffffffffu, sum, 8);
            lrow[i] = lrow[i] * alpha + sum;
            mrow[i] = mnew;
#pragma unroll
            for (int j = 0; j < 4; j++) O[i][j] *= alpha;
            *reinterpret_cast<float4*>(&Ps[ro[i] + tx * 4]) =
                make_float4(s[i][0], s[i][1], s[i][2], s[i][3]);
        }
        __syncthreads();

        // O += P @ V : 8 rows x 4 cols, float4 operands
#pragma unroll 4
        for (int kk4 = 0; kk4 < 16; kk4++) {
            float4 v0 = *reinterpret_cast<const float4*>(&Vs[(kk4 * 4 + 0) * VS_LD + tx * 4]);
            float4 v1 = *reinterpret_cast<const float4*>(&Vs[(kk4 * 4 + 1) * VS_LD + tx * 4]);
            float4 v2 = *reinterpret_cast<const float4*>(&Vs[(kk4 * 4 + 2) * VS_LD + tx * 4]);
            float4 v3 = *reinterpret_cast<const float4*>(&Vs[(kk4 * 4 + 3) * VS_LD + tx * 4]);
#pragma unroll
            for (int i = 0; i < 8; i++) {
                float4 p = *reinterpret_cast<const float4*>(&Ps[ro[i] + kk4 * 4]);
                O[i][0] += p.x * v0.x + p.y * v1.x + p.z * v2.x + p.w * v3.x;
                O[i][1] += p.x * v0.y + p.y * v1.y + p.z * v2.y + p.w * v3.y;
                O[i][2] += p.x * v0.z + p.y * v1.z + p.z * v2.z + p.w * v3.z;
                O[i][3] += p.x * v0.w + p.y * v1.w + p.z * v2.w + p.w * v3.w;
            }
        }
    }

    // epilogue: ctx[b*T + t][h*64 + d]
    const int b = bh / HEADS, h = bh % HEADS;
#pragma unroll
    for (int i = 0; i < 8; i++) {
        const float inv = 1.f / lrow[i];
        float4 o = make_float4(O[i][0] * inv, O[i][1] * inv, O[i][2] * inv, O[i][3] * inv);
        *reinterpret_cast<float4*>(
            &ctx[(size_t)(b * T_SEQ + q0 + rrow[i]) * CDIM + h * DH + tx * 4]) = o;
    }
}

// ---------------- launch ----------------------------------------------------
extern "C" void kernel_launch(void* const* d_in, const int* in_sizes, int n_in,
                              void* d_out, int out_size)
{
    (void)in_sizes; (void)n_in; (void)out_size;
    const float* x  = (const float*)d_in[0];
    const float* Wq = (const float*)d_in[1];
    const float* bq = (const float*)d_in[2];
    const float* Wk = (const float*)d_in[3];
    const float* bk = (const float*)d_in[4];
    const float* Wv = (const float*)d_in[5];
    const float* bv = (const float*)d_in[6];
    const float* Wo = (const float*)d_in[7];
    const float* bo = (const float*)d_in[8];
    float* out = (float*)d_out;

    static float *qp = nullptr, *kp = nullptr, *vp = nullptr, *cp = nullptr;
    if (!qp) {
        cudaGetSymbolAddress((void**)&qp, g_q);
        cudaGetSymbolAddress((void**)&kp, g_k);
        cudaGetSymbolAddress((void**)&vp, g_v);
        cudaGetSymbolAddress((void**)&cp, g_ctx);
        cudaFuncSetAttribute(attn_kernel,
                             cudaFuncAttributeMaxDynamicSharedMemorySize,
                             SMEM_ATTN_BYTES);
    }

    dim3 gblk(256);
    dim3 ggrid(CDIM / 128, MROWS / 128);   // (3, 64)

    gemm_bias_kernel<<<ggrid, gblk>>>(x, Wq, bq, qp, MROWS, CDIM, CDIM, 1);
    gemm_bias_kernel<<<ggrid, gblk>>>(x, Wk, bk, kp, MROWS, CDIM, CDIM, 1);
    gemm_bias_kernel<<<ggrid, gblk>>>(x, Wv, bv, vp, MROWS, CDIM, CDIM, 1);

    dim3 agrid(T_SEQ / BQ, BATCH * HEADS);   // (16, 24)
    attn_kernel<<<agrid, 256, SMEM_ATTN_BYTES>>>(cp);

    gemm_bias_kernel<<<ggrid, gblk>>>(cp, Wo, bo, out, MROWS, CDIM, CDIM, 0);
}

// round 3
// speedup vs baseline: 5.2424x; 1.6947x over previous
#include <cuda_runtime.h>

// Problem constants
#define BATCH   4
#define T_SEQ   2048
#define CDIM    384
#define HEADS   6
#define DH      64
#define MROWS   (BATCH * T_SEQ)        // 8192

// ---------------- scratch (static device globals; no runtime allocation) ----
__device__ float g_q[BATCH * HEADS * T_SEQ * DH];   // [B,H,T,D]
__device__ float g_k[BATCH * HEADS * T_SEQ * DH];
__device__ float g_v[BATCH * HEADS * T_SEQ * DH];
__device__ float g_ctx[MROWS * CDIM];               // [B*T, C]

// ---------------- tiled fp32 GEMM (unchanged from R2) -----------------------
__global__ __launch_bounds__(256, 2) void gemm_bias_kernel(
    const float* __restrict__ A, const float* __restrict__ W,
    const float* __restrict__ bias, float* __restrict__ out,
    int M, int N, int K, int bhtd)
{
    __shared__ float As[16][132];
    __shared__ float Ws[16][128];

    const int tid = threadIdx.x;
    const int n0 = blockIdx.x * 128;
    const int m0 = blockIdx.y * 128;
    const int ty = tid >> 4;
    const int tx = tid & 15;

    float acc[8][8];
#pragma unroll
    for (int i = 0; i < 8; i++)
#pragma unroll
        for (int j = 0; j < 8; j++) acc[i][j] = 0.f;

    for (int k0 = 0; k0 < K; k0 += 16) {
#pragma unroll
        for (int p = 0; p < 2; p++) {
            int idx = tid + 256 * p;
            int row = idx >> 2, c4 = idx & 3;
            float4 a = *reinterpret_cast<const float4*>(&A[(size_t)(m0 + row) * K + k0 + c4 * 4]);
            As[c4 * 4 + 0][row] = a.x;
            As[c4 * 4 + 1][row] = a.y;
            As[c4 * 4 + 2][row] = a.z;
            As[c4 * 4 + 3][row] = a.w;
        }
#pragma unroll
        for (int p = 0; p < 2; p++) {
            int idx = tid + 256 * p;
            int wr = idx >> 5, wc4 = idx & 31;
            *reinterpret_cast<float4*>(&Ws[wr][wc4 * 4]) =
                *reinterpret_cast<const float4*>(&W[(size_t)(k0 + wr) * N + n0 + wc4 * 4]);
        }
        __syncthreads();

#pragma unroll
        for (int kk = 0; kk < 16; kk++) {
            float4 a0 = *reinterpret_cast<const float4*>(&As[kk][ty * 4]);
            float4 a1 = *reinterpret_cast<const float4*>(&As[kk][ty * 4 + 64]);
            float4 b0 = *reinterpret_cast<const float4*>(&Ws[kk][tx * 4]);
            float4 b1 = *reinterpret_cast<const float4*>(&Ws[kk][tx * 4 + 64]);
            float av[8] = {a0.x, a0.y, a0.z, a0.w, a1.x, a1.y, a1.z, a1.w};
            float bv[8] = {b0.x, b0.y, b0.z, b0.w, b1.x, b1.y, b1.z, b1.w};
#pragma unroll
            for (int i = 0; i < 8; i++)
#pragma unroll
                for (int j = 0; j < 8; j++) acc[i][j] += av[i] * bv[j];
        }
        __syncthreads();
    }

#pragma unroll
    for (int i = 0; i < 8; i++) {
        const int m = m0 + ty * 4 + ((i < 4) ? i : 60 + i);
#pragma unroll
        for (int jh = 0; jh < 2; jh++) {
            const int n = n0 + tx * 4 + jh * 64;
            float4 v;
            v.x = acc[i][jh * 4 + 0] + bias[n + 0];
            v.y = acc[i][jh * 4 + 1] + bias[n + 1];
            v.z = acc[i][jh * 4 + 2] + bias[n + 2];
            v.w = acc[i][jh * 4 + 3] + bias[n + 3];
            if (bhtd) {
                const int b = m >> 11, t = m & 2047;
                const int h = n >> 6, d = n & 63;
                *reinterpret_cast<float4*>(
                    &out[(((size_t)(b * HEADS + h) * T_SEQ + t) * DH) + d]) = v;
            } else {
                *reinterpret_cast<float4*>(&out[(size_t)m * N + n]) = v;
            }
        }
    }
}

// ---------------- tf32 tensor-core causal flash attention -------------------
#define BQ 128
#define BK 64
#define KS_LD 68
#define VS_LD 72
#define PS_LD 68
#define KS_OFF 0
#define VS_OFF (64 * KS_LD)                       // 4352
#define PS_OFF (VS_OFF + 64 * VS_LD)              // 8960
#define ATTN_SMEM_FLOATS (PS_OFF + 128 * PS_LD)   // 17664
#define ATTN_SMEM_BYTES  (ATTN_SMEM_FLOATS * 4)   // 70656

__device__ __forceinline__ unsigned f2tf32(float x) {
    unsigned u;
    asm("cvt.rna.tf32.f32 %0, %1;" : "=r"(u) : "f"(x));
    return u;
}

__device__ __forceinline__ void mma_tf32(float c[4], const unsigned a[4],
                                         unsigned b0, unsigned b1) {
    asm volatile(
        "mma.sync.aligned.m16n8k8.row.col.f32.tf32.tf32.f32 "
        "{%0,%1,%2,%3}, {%4,%5,%6,%7}, {%8,%9}, {%0,%1,%2,%3};\n"
        : "+f"(c[0]), "+f"(c[1]), "+f"(c[2]), "+f"(c[3])
        : "r"(a[0]), "r"(a[1]), "r"(a[2]), "r"(a[3]), "r"(b0), "r"(b1));
}

__global__ void __launch_bounds__(256, 1) attn_kernel(float* __restrict__ ctx)
{
    extern __shared__ float sm[];
    float* Ks = sm + KS_OFF;   // [64][68]  K natural [token][d]
    float* Vs = sm + VS_OFF;   // [64][72]  V natural [token][d]
    float* Ps = sm + PS_OFF;   // [128][68] Q staging, then per-warp P

    const int tid  = threadIdx.x;
    const int lane = tid & 31;
    const int w    = tid >> 5;           // warp 0..7, owns rows w*16..w*16+15
    const int gid  = lane >> 2;          // 0..7
    const int tig  = lane & 3;           // 0..3

    const int bh = blockIdx.y;
    const int qi = gridDim.x - 1 - blockIdx.x;   // heavy blocks first
    const int q0 = qi * BQ;

    const float* qb = g_q + (size_t)bh * T_SEQ * DH;
    const float* kb = g_k + (size_t)bh * T_SEQ * DH;
    const float* vb = g_v + (size_t)bh * T_SEQ * DH;

    // ---- stage Q (pre-scaled, tf32-rounded) into Ps, then frags to regs ----
#pragma unroll
    for (int p = 0; p < 8; p++) {
        int idx = tid + 256 * p;             // 2048 float4
        int row = idx >> 4, c4 = idx & 15;
        float4 v = *reinterpret_cast<const float4*>(&qb[(size_t)(q0 + row) * DH + c4 * 4]);
        v.x = __uint_as_float(f2tf32(v.x * 0.125f));
        v.y = __uint_as_float(f2tf32(v.y * 0.125f));
        v.z = __uint_as_float(f2tf32(v.z * 0.125f));
        v.w = __uint_as_float(f2tf32(v.w * 0.125f));
        *reinterpret_cast<float4*>(&Ps[row * PS_LD + c4 * 4]) = v;
    }
    __syncthreads();

    const int arow = w * 16 + gid;           // within-tile row of this thread
    unsigned qf[8][4];
#pragma unroll
    for (int s = 0; s < 8; s++) {
        const float* base = &Ps[arow * PS_LD + s * 8 + tig];
        qf[s][0] = __float_as_uint(base[0]);
        qf[s][1] = __float_as_uint(base[8 * PS_LD]);
        qf[s][2] = __float_as_uint(base[4]);
        qf[s][3] = __float_as_uint(base[8 * PS_LD + 4]);
    }

    float O[8][4];
#pragma unroll
    for (int nt = 0; nt < 8; nt++)
#pragma unroll
        for (int j = 0; j < 4; j++) O[nt][j] = 0.f;
    float mA = -1e30f, mB = -1e30f, lA = 0.f, lB = 0.f;

    // ---- prefetch tile 0 ----
    float4 kr[4], vr[4];
#pragma unroll
    for (int p = 0; p < 4; p++) {
        int idx = tid + 256 * p;
        int row = idx >> 4, c4 = idx & 15;
        kr[p] = *reinterpret_cast<const float4*>(&kb[(size_t)row * DH + c4 * 4]);
        vr[p] = *reinterpret_cast<const float4*>(&vb[(size_t)row * DH + c4 * 4]);
    }

    const int ntiles = 2 * qi + 2;
    for (int kt = 0; kt < ntiles; kt++) {
        const int k0 = kt * BK;
        __syncthreads();
        // commit staged tile to smem (tf32-rounded)
#pragma unroll
        for (int p = 0; p < 4; p++) {
            int idx = tid + 256 * p;
            int row = idx >> 4, c4 = idx & 15;
            float4 k4 = kr[p], v4 = vr[p];
            k4.x = __uint_as_float(f2tf32(k4.x)); k4.y = __uint_as_float(f2tf32(k4.y));
            k4.z = __uint_as_float(f2tf32(k4.z)); k4.w = __uint_as_float(f2tf32(k4.w));
            v4.x = __uint_as_float(f2tf32(v4.x)); v4.y = __uint_as_float(f2tf32(v4.y));
            v4.z = __uint_as_float(f2tf32(v4.z)); v4.w = __uint_as_float(f2tf32(v4.w));
            *reinterpret_cast<float4*>(&Ks[row * KS_LD + c4 * 4]) = k4;
            *reinterpret_cast<float4*>(&Vs[row * VS_LD + c4 * 4]) = v4;
        }
        __syncthreads();
        // prefetch next tile
        if (kt + 1 < ntiles) {
            const float* kn = kb + (size_t)(k0 + BK) * DH;
            const float* vn = vb + (size_t)(k0 + BK) * DH;
#pragma unroll
            for (int p = 0; p < 4; p++) {
                int idx = tid + 256 * p;
                int row = idx >> 4, c4 = idx & 15;
                kr[p] = *reinterpret_cast<const float4*>(&kn[(size_t)row * DH + c4 * 4]);
                vr[p] = *reinterpret_cast<const float4*>(&vn[(size_t)row * DH + c4 * 4]);
            }
        }

        // warps entirely above the diagonal skip compute
        if (k0 > q0 + w * 16 + 15) continue;

        // ---- S = Q K^T ----
        float S[8][4];
#pragma unroll
        for (int nt = 0; nt < 8; nt++)
#pragma unroll
            for (int j = 0; j < 4; j++) S[nt][j] = 0.f;
#pragma unroll
        for (int s = 0; s < 8; s++) {
#pragma unroll
            for (int nt = 0; nt < 8; nt++) {
                const float* bb = &Ks[(nt * 8 + gid) * KS_LD + s * 8 + tig];
                mma_tf32(S[nt], qf[s], __float_as_uint(bb[0]), __float_as_uint(bb[4]));
            }
        }

        // ---- causal mask ----
        const int rA = q0 + arow;
        const int rB = rA + 8;
        if (k0 + BK - 1 > rA) {
#pragma unroll
            for (int nt = 0; nt < 8; nt++) {
                const int c0 = k0 + nt * 8 + 2 * tig;
                if (c0     > rA) S[nt][0] = -1e30f;
                if (c0 + 1 > rA) S[nt][1] = -1e30f;
                if (c0     > rB) S[nt][2] = -1e30f;
                if (c0 + 1 > rB) S[nt][3] = -1e30f;
            }
        }

        // ---- online softmax (rows rA, rB) ----
        float mxA = -1e30f, mxB = -1e30f;
#pragma unroll
        for (int nt = 0; nt < 8; nt++) {
            mxA = fmaxf(mxA, fmaxf(S[nt][0], S[nt][1]));
            mxB = fmaxf(mxB, fmaxf(S[nt][2], S[nt][3]));
        }
        mxA = fmaxf(mxA, __shfl_xor_sync(0xffffffffu, mxA, 1));
        mxA = fmaxf(mxA, __shfl_xor_sync(0xffffffffu, mxA, 2));
        mxB = fmaxf(mxB, __shfl_xor_sync(0xffffffffu, mxB, 1));
        mxB = fmaxf(mxB, __shfl_xor_sync(0xffffffffu, mxB, 2));

        const float mnA = fmaxf(mA, mxA), mnB = fmaxf(mB, mxB);
        const float aA = __expf(mA - mnA), aB = __expf(mB - mnB);
        float sA = 0.f, sB = 0.f;
#pragma unroll
        for (int nt = 0; nt < 8; nt++) {
            S[nt][0] = __expf(S[nt][0] - mnA);
            S[nt][1] = __expf(S[nt][1] - mnA);
            S[nt][2] = __expf(S[nt][2] - mnB);
            S[nt][3] = __expf(S[nt][3] - mnB);
            sA += S[nt][0] + S[nt][1];
            sB += S[nt][2] + S[nt][3];
        }
        sA += __shfl_xor_sync(0xffffffffu, sA, 1);
        sA += __shfl_xor_sync(0xffffffffu, sA, 2);
        sB += __shfl_xor_sync(0xffffffffu, sB, 1);
        sB += __shfl_xor_sync(0xffffffffu, sB, 2);
        lA = lA * aA + sA;  lB = lB * aB + sB;
        mA = mnA;           mB = mnB;
#pragma unroll
        for (int nt = 0; nt < 8; nt++) {
            O[nt][0] *= aA; O[nt][1] *= aA;
            O[nt][2] *= aB; O[nt][3] *= aB;
        }

        // ---- P: C-frag -> smem (warp-private rows) -> A-frag ----
#pragma unroll
        for (int nt = 0; nt < 8; nt++) {
            *reinterpret_cast<float2*>(&Ps[arow * PS_LD + nt * 8 + 2 * tig]) =
                make_float2(S[nt][0], S[nt][1]);
            *reinterpret_cast<float2*>(&Ps[(arow + 8) * PS_LD + nt * 8 + 2 * tig]) =
                make_float2(S[nt][2], S[nt][3]);
        }
        __syncwarp();

        // ---- O += P V ----
#pragma unroll
        for (int s = 0; s < 8; s++) {
            unsigned pa[4];
            const float* pb = &Ps[arow * PS_LD + s * 8 + tig];
            pa[0] = __float_as_uint(pb[0]);
            pa[1] = __float_as_uint(pb[8 * PS_LD]);
            pa[2] = __float_as_uint(pb[4]);
            pa[3] = __float_as_uint(pb[8 * PS_LD + 4]);
#pragma unroll
            for (int nt = 0; nt < 8; nt++) {
                const float* vv = &Vs[(s * 8 + tig) * VS_LD + nt * 8 + gid];
                mma_tf32(O[nt], pa, __float_as_uint(vv[0]),
                         __float_as_uint(vv[4 * VS_LD]));
            }
        }
    }

    // ---- epilogue ----
    const float iA = 1.f / lA, iB = 1.f / lB;
    const int b = bh / HEADS, h = bh % HEADS;
    const size_t rowA = (size_t)(b * T_SEQ + q0 + arow) * CDIM + h * DH;
    const size_t rowB = rowA + (size_t)8 * CDIM;
#pragma unroll
    for (int nt = 0; nt < 8; nt++) {
        *reinterpret_cast<float2*>(&ctx[rowA + nt * 8 + 2 * tig]) =
            make_float2(O[nt][0] * iA, O[nt][1] * iA);
        *reinterpret_cast<float2*>(&ctx[rowB + nt * 8 + 2 * tig]) =
            make_float2(O[nt][2] * iB, O[nt][3] * iB);
    }
}

// ---------------- launch ----------------------------------------------------
extern "C" void kernel_launch(void* const* d_in, const int* in_sizes, int n_in,
                              void* d_out, int out_size)
{
    (void)in_sizes; (void)n_in; (void)out_size;
    const float* x  = (const float*)d_in[0];
    const float* Wq = (const float*)d_in[1];
    const float* bq = (const float*)d_in[2];
    const float* Wk = (const float*)d_in[3];
    const float* bk = (const float*)d_in[4];
    const float* Wv = (const float*)d_in[5];
    const float* bv = (const float*)d_in[6];
    const float* Wo = (const float*)d_in[7];
    const float* bo = (const float*)d_in[8];
    float* out = (float*)d_out;

    static float *qp = nullptr, *kp = nullptr, *vp = nullptr, *cp = nullptr;
    if (!qp) {
        cudaGetSymbolAddress((void**)&qp, g_q);
        cudaGetSymbolAddress((void**)&kp, g_k);
        cudaGetSymbolAddress((void**)&vp, g_v);
        cudaGetSymbolAddress((void**)&cp, g_ctx);
        cudaFuncSetAttribute(attn_kernel,
                             cudaFuncAttributeMaxDynamicSharedMemorySize,
                             ATTN_SMEM_BYTES);
    }

    dim3 gblk(256);
    dim3 ggrid(CDIM / 128, MROWS / 128);   // (3, 64)

    gemm_bias_kernel<<<ggrid, gblk>>>(x, Wq, bq, qp, MROWS, CDIM, CDIM, 1);
    gemm_bias_kernel<<<ggrid, gblk>>>(x, Wk, bk, kp, MROWS, CDIM, CDIM, 1);
    gemm_bias_kernel<<<ggrid, gblk>>>(x, Wv, bv, vp, MROWS, CDIM, CDIM, 1);

    dim3 agrid(T_SEQ / BQ, BATCH * HEADS);   // (16, 24)
    attn_kernel<<<agrid, 256, ATTN_SMEM_BYTES>>>(cp);

    gemm_bias_kernel<<<ggrid, gblk>>>(cp, Wo, bo, out, MROWS, CDIM, CDIM, 0);
}

// round 4
// speedup vs baseline: 8.4052x; 1.6033x over previous
#include <cuda_runtime.h>

// Problem constants
#define BATCH   4
#define T_SEQ   2048
#define CDIM    384
#define HEADS   6
#define DH      64
#define MROWS   (BATCH * T_SEQ)        // 8192

// ---------------- scratch (static device globals; no runtime allocation) ----
__device__ float g_q[BATCH * HEADS * T_SEQ * DH];   // [B,H,T,D]
__device__ float g_k[BATCH * HEADS * T_SEQ * DH];
__device__ float g_v[BATCH * HEADS * T_SEQ * DH];
__device__ float g_ctx[MROWS * CDIM];               // [B*T, C]

__device__ __forceinline__ unsigned f2tf32(float x) {
    unsigned u;
    asm("cvt.rna.tf32.f32 %0, %1;" : "=r"(u) : "f"(x));
    return u;
}
__device__ __forceinline__ float rtf(float x) { return __uint_as_float(f2tf32(x)); }

__device__ __forceinline__ void mma_tf32(float c[4], const unsigned a[4],
                                         unsigned b0, unsigned b1) {
    asm volatile(
        "mma.sync.aligned.m16n8k8.row.col.f32.tf32.tf32.f32 "
        "{%0,%1,%2,%3}, {%4,%5,%6,%7}, {%8,%9}, {%0,%1,%2,%3};\n"
        : "+f"(c[0]), "+f"(c[1]), "+f"(c[2]), "+f"(c[3])
        : "r"(a[0]), "r"(a[1]), "r"(a[2]), "r"(a[3]), "r"(b0), "r"(b1));
}

// ---------------- tf32 tensor-core GEMM: out = A[M,K] @ W[K,N] + bias -------
// Block 128x128, BK=32, 256 threads (8 warps, 2M x 4N), warp tile 64x32.
#define AS_LD 36
#define WS_LD 132
__global__ __launch_bounds__(256, 2) void gemm_tf32_kernel(
    const float* __restrict__ A, const float* __restrict__ W,
    const float* __restrict__ bias, float* __restrict__ out,
    int M, int N, int K, int bhtd)
{
    __shared__ float As[128 * AS_LD];   // [m][k] padded
    __shared__ float Ws[32 * WS_LD];    // [k][n] padded

    const int tid  = threadIdx.x;
    const int lane = tid & 31;
    const int w    = tid >> 5;
    const int gid  = lane >> 2;
    const int tig  = lane & 3;
    const int wm0  = (w & 1) * 64;
    const int wn0  = (w >> 1) * 32;
    const int n0   = blockIdx.x * 128;
    const int m0   = blockIdx.y * 128;

    float acc[4][4][4];
#pragma unroll
    for (int mt = 0; mt < 4; mt++)
#pragma unroll
        for (int nt = 0; nt < 4; nt++)
#pragma unroll
            for (int j = 0; j < 4; j++) acc[mt][nt][j] = 0.f;

    // prefetch first K-slab to registers
    float4 ar[4], wrg[4];
#pragma unroll
    for (int p = 0; p < 4; p++) {
        int idx = tid + 256 * p;
        int row = idx >> 3, c4 = idx & 7;      // A: 128 rows x 8 float4
        ar[p] = *reinterpret_cast<const float4*>(&A[(size_t)(m0 + row) * K + c4 * 4]);
        int kk = idx >> 5, wc4 = idx & 31;     // W: 32 rows x 32 float4
        wrg[p] = *reinterpret_cast<const float4*>(&W[(size_t)kk * N + n0 + wc4 * 4]);
    }

    const int niter = K / 32;
    for (int kt = 0; kt < niter; kt++) {
        __syncthreads();
#pragma unroll
        for (int p = 0; p < 4; p++) {
            int idx = tid + 256 * p;
            int row = idx >> 3, c4 = idx & 7;
            float4 a = ar[p];
            a.x = rtf(a.x); a.y = rtf(a.y); a.z = rtf(a.z); a.w = rtf(a.w);
            *reinterpret_cast<float4*>(&As[row * AS_LD + c4 * 4]) = a;
            int kk = idx >> 5, wc4 = idx & 31;
            float4 wv = wrg[p];
            wv.x = rtf(wv.x); wv.y = rtf(wv.y); wv.z = rtf(wv.z); wv.w = rtf(wv.w);
            *reinterpret_cast<float4*>(&Ws[kk * WS_LD + wc4 * 4]) = wv;
        }
        __syncthreads();

        if (kt + 1 < niter) {
            const int k0n = (kt + 1) * 32;
#pragma unroll
            for (int p = 0; p < 4; p++) {
                int idx = tid + 256 * p;
                int row = idx >> 3, c4 = idx & 7;
                ar[p] = *reinterpret_cast<const float4*>(
                    &A[(size_t)(m0 + row) * K + k0n + c4 * 4]);
                int kk = idx >> 5, wc4 = idx & 31;
                wrg[p] = *reinterpret_cast<const float4*>(
                    &W[(size_t)(k0n + kk) * N + n0 + wc4 * 4]);
            }
        }

#pragma unroll
        for (int ks = 0; ks < 4; ks++) {
            unsigned af[4][4];
#pragma unroll
            for (int mt = 0; mt < 4; mt++) {
                const float* ab = &As[(wm0 + mt * 16 + gid) * AS_LD + ks * 8 + tig];
                af[mt][0] = __float_as_uint(ab[0]);
                af[mt][1] = __float_as_uint(ab[8 * AS_LD]);
                af[mt][2] = __float_as_uint(ab[4]);
                af[mt][3] = __float_as_uint(ab[8 * AS_LD + 4]);
            }
            unsigned bf[4][2];
#pragma unroll
            for (int nt = 0; nt < 4; nt++) {
                const float* bb = &Ws[(ks * 8 + tig) * WS_LD + wn0 + nt * 8 + gid];
                bf[nt][0] = __float_as_uint(bb[0]);
                bf[nt][1] = __float_as_uint(bb[4 * WS_LD]);
            }
#pragma unroll
            for (int mt = 0; mt < 4; mt++)
#pragma unroll
                for (int nt = 0; nt < 4; nt++)
                    mma_tf32(acc[mt][nt], af[mt], bf[nt][0], bf[nt][1]);
        }
    }

    // epilogue
#pragma unroll
    for (int mt = 0; mt < 4; mt++) {
#pragma unroll
        for (int half = 0; half < 2; half++) {
            const int m = m0 + wm0 + mt * 16 + gid + half * 8;
#pragma unroll
            for (int nt = 0; nt < 4; nt++) {
                const int n = n0 + wn0 + nt * 8 + 2 * tig;
                float2 v;
                v.x = acc[mt][nt][half * 2 + 0] + bias[n + 0];
                v.y = acc[mt][nt][half * 2 + 1] + bias[n + 1];
                if (bhtd) {
                    const int b = m >> 11, t = m & 2047;
                    const int h = n >> 6, d = n & 63;
                    *reinterpret_cast<float2*>(
                        &out[(((size_t)(b * HEADS + h) * T_SEQ + t) * DH) + d]) = v;
                } else {
                    *reinterpret_cast<float2*>(&out[(size_t)m * N + n]) = v;
                }
            }
        }
    }
}

// ---------------- tf32 tensor-core causal flash attention (unchanged R3) ----
#define BQ 128
#define BK 64
#define KS_LD 68
#define VS_LD 72
#define PS_LD 68
#define KS_OFF 0
#define VS_OFF (64 * KS_LD)
#define PS_OFF (VS_OFF + 64 * VS_LD)
#define ATTN_SMEM_FLOATS (PS_OFF + 128 * PS_LD)
#define ATTN_SMEM_BYTES  (ATTN_SMEM_FLOATS * 4)

__global__ void __launch_bounds__(256, 1) attn_kernel(float* __restrict__ ctx)
{
    extern __shared__ float sm[];
    float* Ks = sm + KS_OFF;
    float* Vs = sm + VS_OFF;
    float* Ps = sm + PS_OFF;

    const int tid  = threadIdx.x;
    const int lane = tid & 31;
    const int w    = tid >> 5;
    const int gid  = lane >> 2;
    const int tig  = lane & 3;

    const int bh = blockIdx.y;
    const int qi = gridDim.x - 1 - blockIdx.x;
    const int q0 = qi * BQ;

    const float* qb = g_q + (size_t)bh * T_SEQ * DH;
    const float* kb = g_k + (size_t)bh * T_SEQ * DH;
    const float* vb = g_v + (size_t)bh * T_SEQ * DH;

#pragma unroll
    for (int p = 0; p < 8; p++) {
        int idx = tid + 256 * p;
        int row = idx >> 4, c4 = idx & 15;
        float4 v = *reinterpret_cast<const float4*>(&qb[(size_t)(q0 + row) * DH + c4 * 4]);
        v.x = rtf(v.x * 0.125f);
        v.y = rtf(v.y * 0.125f);
        v.z = rtf(v.z * 0.125f);
        v.w = rtf(v.w * 0.125f);
        *reinterpret_cast<float4*>(&Ps[row * PS_LD + c4 * 4]) = v;
    }
    __syncthreads();

    const int arow = w * 16 + gid;
    unsigned qf[8][4];
#pragma unroll
    for (int s = 0; s < 8; s++) {
        const float* base = &Ps[arow * PS_LD + s * 8 + tig];
        qf[s][0] = __float_as_uint(base[0]);
        qf[s][1] = __float_as_uint(base[8 * PS_LD]);
        qf[s][2] = __float_as_uint(base[4]);
        qf[s][3] = __float_as_uint(base[8 * PS_LD + 4]);
    }

    float O[8][4];
#pragma unroll
    for (int nt = 0; nt < 8; nt++)
#pragma unroll
        for (int j = 0; j < 4; j++) O[nt][j] = 0.f;
    float mA = -1e30f, mB = -1e30f, lA = 0.f, lB = 0.f;

    float4 kr[4], vr[4];
#pragma unroll
    for (int p = 0; p < 4; p++) {
        int idx = tid + 256 * p;
        int row = idx >> 4, c4 = idx & 15;
        kr[p] = *reinterpret_cast<const float4*>(&kb[(size_t)row * DH + c4 * 4]);
        vr[p] = *reinterpret_cast<const float4*>(&vb[(size_t)row * DH + c4 * 4]);
    }

    const int ntiles = 2 * qi + 2;
    for (int kt = 0; kt < ntiles; kt++) {
        const int k0 = kt * BK;
        __syncthreads();
#pragma unroll
        for (int p = 0; p < 4; p++) {
            int idx = tid + 256 * p;
            int row = idx >> 4, c4 = idx & 15;
            float4 k4 = kr[p], v4 = vr[p];
            k4.x = rtf(k4.x); k4.y = rtf(k4.y); k4.z = rtf(k4.z); k4.w = rtf(k4.w);
            v4.x = rtf(v4.x); v4.y = rtf(v4.y); v4.z = rtf(v4.z); v4.w = rtf(v4.w);
            *reinterpret_cast<float4*>(&Ks[row * KS_LD + c4 * 4]) = k4;
            *reinterpret_cast<float4*>(&Vs[row * VS_LD + c4 * 4]) = v4;
        }
        __syncthreads();
        if (kt + 1 < ntiles) {
            const float* kn = kb + (size_t)(k0 + BK) * DH;
            const float* vn = vb + (size_t)(k0 + BK) * DH;
#pragma unroll
            for (int p = 0; p < 4; p++) {
                int idx = tid + 256 * p;
                int row = idx >> 4, c4 = idx & 15;
                kr[p] = *reinterpret_cast<const float4*>(&kn[(size_t)row * DH + c4 * 4]);
                vr[p] = *reinterpret_cast<const float4*>(&vn[(size_t)row * DH + c4 * 4]);
            }
        }

        if (k0 > q0 + w * 16 + 15) continue;

        float S[8][4];
#pragma unroll
        for (int nt = 0; nt < 8; nt++)
#pragma unroll
            for (int j = 0; j < 4; j++) S[nt][j] = 0.f;
#pragma unroll
        for (int s = 0; s < 8; s++) {
#pragma unroll
            for (int nt = 0; nt < 8; nt++) {
                const float* bb = &Ks[(nt * 8 + gid) * KS_LD + s * 8 + tig];
                mma_tf32(S[nt], qf[s], __float_as_uint(bb[0]), __float_as_uint(bb[4]));
            }
        }

        const int rA = q0 + arow;
        const int rB = rA + 8;
        if (k0 + BK - 1 > rA) {
#pragma unroll
            for (int nt = 0; nt < 8; nt++) {
                const int c0 = k0 + nt * 8 + 2 * tig;
                if (c0     > rA) S[nt][0] = -1e30f;
                if (c0 + 1 > rA) S[nt][1] = -1e30f;
                if (c0     > rB) S[nt][2] = -1e30f;
                if (c0 + 1 > rB) S[nt][3] = -1e30f;
            }
        }

        float mxA = -1e30f, mxB = -1e30f;
#pragma unroll
        for (int nt = 0; nt < 8; nt++) {
            mxA = fmaxf(mxA, fmaxf(S[nt][0], S[nt][1]));
            mxB = fmaxf(mxB, fmaxf(S[nt][2], S[nt][3]));
        }
        mxA = fmaxf(mxA, __shfl_xor_sync(0xffffffffu, mxA, 1));
        mxA = fmaxf(mxA, __shfl_xor_sync(0xffffffffu, mxA, 2));
        mxB = fmaxf(mxB, __shfl_xor_sync(0xffffffffu, mxB, 1));
        mxB = fmaxf(mxB, __shfl_xor_sync(0xffffffffu, mxB, 2));

        const float mnA = fmaxf(mA, mxA), mnB = fmaxf(mB, mxB);
        const float aA = __expf(mA - mnA), aB = __expf(mB - mnB);
        float sA = 0.f, sB = 0.f;
#pragma unroll
        for (int nt = 0; nt < 8; nt++) {
            S[nt][0] = __expf(S[nt][0] - mnA);
            S[nt][1] = __expf(S[nt][1] - mnA);
            S[nt][2] = __expf(S[nt][2] - mnB);
            S[nt][3] = __expf(S[nt][3] - mnB);
            sA += S[nt][0] + S[nt][1];
            sB += S[nt][2] + S[nt][3];
        }
        sA += __shfl_xor_sync(0xffffffffu, sA, 1);
        sA += __shfl_xor_sync(0xffffffffu, sA, 2);
        sB += __shfl_xor_sync(0xffffffffu, sB, 1);
        sB += __shfl_xor_sync(0xffffffffu, sB, 2);
        lA = lA * aA + sA;  lB = lB * aB + sB;
        mA = mnA;           mB = mnB;
#pragma unroll
        for (int nt = 0; nt < 8; nt++) {
            O[nt][0] *= aA; O[nt][1] *= aA;
            O[nt][2] *= aB; O[nt][3] *= aB;
        }

#pragma unroll
        for (int nt = 0; nt < 8; nt++) {
            *reinterpret_cast<float2*>(&Ps[arow * PS_LD + nt * 8 + 2 * tig]) =
                make_float2(S[nt][0], S[nt][1]);
            *reinterpret_cast<float2*>(&Ps[(arow + 8) * PS_LD + nt * 8 + 2 * tig]) =
                make_float2(S[nt][2], S[nt][3]);
        }
        __syncwarp();

#pragma unroll
        for (int s = 0; s < 8; s++) {
            unsigned pa[4];
            const float* pb = &Ps[arow * PS_LD + s * 8 + tig];
            pa[0] = __float_as_uint(pb[0]);
            pa[1] = __float_as_uint(pb[8 * PS_LD]);
            pa[2] = __float_as_uint(pb[4]);
            pa[3] = __float_as_uint(pb[8 * PS_LD + 4]);
#pragma unroll
            for (int nt = 0; nt < 8; nt++) {
                const float* vv = &Vs[(s * 8 + tig) * VS_LD + nt * 8 + gid];
                mma_tf32(O[nt], pa, __float_as_uint(vv[0]),
                         __float_as_uint(vv[4 * VS_LD]));
            }
        }
    }

    const float iA = 1.f / lA, iB = 1.f / lB;
    const int b = bh / HEADS, h = bh % HEADS;
    const size_t rowA = (size_t)(b * T_SEQ + q0 + arow) * CDIM + h * DH;
    const size_t rowB = rowA + (size_t)8 * CDIM;
#pragma unroll
    for (int nt = 0; nt < 8; nt++) {
        *reinterpret_cast<float2*>(&ctx[rowA + nt * 8 + 2 * tig]) =
            make_float2(O[nt][0] * iA, O[nt][1] * iA);
        *reinterpret_cast<float2*>(&ctx[rowB + nt * 8 + 2 * tig]) =
            make_float2(O[nt][2] * iB, O[nt][3] * iB);
    }
}

// ---------------- launch ----------------------------------------------------
extern "C" void kernel_launch(void* const* d_in, const int* in_sizes, int n_in,
                              void* d_out, int out_size)
{
    (void)in_sizes; (void)n_in; (void)out_size;
    const float* x  = (const float*)d_in[0];
    const float* Wq = (const float*)d_in[1];
    const float* bq = (const float*)d_in[2];
    const float* Wk = (const float*)d_in[3];
    const float* bk = (const float*)d_in[4];
    const float* Wv = (const float*)d_in[5];
    const float* bv = (const float*)d_in[6];
    const float* Wo = (const float*)d_in[7];
    const float* bo = (const float*)d_in[8];
    float* out = (float*)d_out;

    static float *qp = nullptr, *kp = nullptr, *vp = nullptr, *cp = nullptr;
    if (!qp) {
        cudaGetSymbolAddress((void**)&qp, g_q);
        cudaGetSymbolAddress((void**)&kp, g_k);
        cudaGetSymbolAddress((void**)&vp, g_v);
        cudaGetSymbolAddress((void**)&cp, g_ctx);
        cudaFuncSetAttribute(attn_kernel,
                             cudaFuncAttributeMaxDynamicSharedMemorySize,
                             ATTN_SMEM_BYTES);
    }

    dim3 gblk(256);
    dim3 ggrid(CDIM / 128, MROWS / 128);   // (3, 64)

    gemm_tf32_kernel<<<ggrid, gblk>>>(x, Wq, bq, qp, MROWS, CDIM, CDIM, 1);
    gemm_tf32_kernel<<<ggrid, gblk>>>(x, Wk, bk, kp, MROWS, CDIM, CDIM, 1);
    gemm_tf32_kernel<<<ggrid, gblk>>>(x, Wv, bv, vp, MROWS, CDIM, CDIM, 1);

    dim3 agrid(T_SEQ / BQ, BATCH * HEADS);   // (16, 24)
    attn_kernel<<<agrid, 256, ATTN_SMEM_BYTES>>>(cp);

    gemm_tf32_kernel<<<ggrid, gblk>>>(cp, Wo, bo, out, MROWS, CDIM, CDIM, 0);
}

// round 6
// speedup vs baseline: 8.4665x; 1.0073x over previous
#include <cuda_runtime.h>

// Problem constants
#define BATCH   4
#define T_SEQ   2048
#define CDIM    384
#define HEADS   6
#define DH      64
#define MROWS   (BATCH * T_SEQ)        // 8192

typedef unsigned int u32;

// ---------------- scratch (static device globals; no runtime allocation) ----
__device__ float g_q[BATCH * HEADS * T_SEQ * DH];   // [B,H,T,D] (tf32-rounded, pre-scaled)
__device__ float g_k[BATCH * HEADS * T_SEQ * DH];   // [B,H,T,D] (tf32-rounded)
__device__ float g_v[BATCH * HEADS * T_SEQ * DH];   // [B,H,T,D] (tf32-rounded)
__device__ float g_ctx[MROWS * CDIM];               // [B*T, C]

__device__ __forceinline__ unsigned f2tf32(float x) {
    unsigned u;
    asm("cvt.rna.tf32.f32 %0, %1;" : "=r"(u) : "f"(x));
    return u;
}
__device__ __forceinline__ float rtf(float x) { return __uint_as_float(f2tf32(x)); }

__device__ __forceinline__ void mma_tf32(float c[4], const unsigned a[4],
                                         unsigned b0, unsigned b1) {
    asm volatile(
        "mma.sync.aligned.m16n8k8.row.col.f32.tf32.tf32.f32 "
        "{%0,%1,%2,%3}, {%4,%5,%6,%7}, {%8,%9}, {%0,%1,%2,%3};\n"
        : "+f"(c[0]), "+f"(c[1]), "+f"(c[2]), "+f"(c[3])
        : "r"(a[0]), "r"(a[1]), "r"(a[2]), "r"(a[3]), "r"(b0), "r"(b1));
}

__device__ __forceinline__ void cp_async16(u32 saddr, const void* gptr) {
    asm volatile("cp.async.cg.shared.global [%0], [%1], 16;"
                 :: "r"(saddr), "l"(gptr));
}
__device__ __forceinline__ void cp_commit() {
    asm volatile("cp.async.commit_group;");
}
__device__ __forceinline__ void cp_wait1() {
    asm volatile("cp.async.wait_group 1;");
}
__device__ __forceinline__ void cp_wait0() {
    asm volatile("cp.async.wait_group 0;");
}

// ---------------- tf32 tensor-core GEMM: out = A[M,K] @ W[K,N] + bias -------
// Block 128x128, BK=32, 256 threads (8 warps, 2M x 4N), warp tile 64x32.
// bhtd==1: scatter to [B,H,T,D], value = rtf((acc+bias)*oscale)
#define AS_LD 36
#define WS_LD 132
__global__ __launch_bounds__(256, 2) void gemm_tf32_kernel(
    const float* __restrict__ A, const float* __restrict__ W,
    const float* __restrict__ bias, float* __restrict__ out,
    int M, int N, int K, int bhtd, float oscale)
{
    __shared__ float As[128 * AS_LD];   // [m][k] padded
    __shared__ float Ws[32 * WS_LD];    // [k][n] padded

    const int tid  = threadIdx.x;
    const int lane = tid & 31;
    const int w    = tid >> 5;
    const int gid  = lane >> 2;
    const int tig  = lane & 3;
    const int wm0  = (w & 1) * 64;
    const int wn0  = (w >> 1) * 32;
    const int n0   = blockIdx.x * 128;
    const int m0   = blockIdx.y * 128;

    float acc[4][4][4];
#pragma unroll
    for (int mt = 0; mt < 4; mt++)
#pragma unroll
        for (int nt = 0; nt < 4; nt++)
#pragma unroll
            for (int j = 0; j < 4; j++) acc[mt][nt][j] = 0.f;

    float4 ar[4], wrg[4];
#pragma unroll
    for (int p = 0; p < 4; p++) {
        int idx = tid + 256 * p;
        int row = idx >> 3, c4 = idx & 7;
        ar[p] = *reinterpret_cast<const float4*>(&A[(size_t)(m0 + row) * K + c4 * 4]);
        int kk = idx >> 5, wc4 = idx & 31;
        wrg[p] = *reinterpret_cast<const float4*>(&W[(size_t)kk * N + n0 + wc4 * 4]);
    }

    const int niter = K / 32;
    for (int kt = 0; kt < niter; kt++) {
        __syncthreads();
#pragma unroll
        for (int p = 0; p < 4; p++) {
            int idx = tid + 256 * p;
            int row = idx >> 3, c4 = idx & 7;
            float4 a = ar[p];
            a.x = rtf(a.x); a.y = rtf(a.y); a.z = rtf(a.z); a.w = rtf(a.w);
            *reinterpret_cast<float4*>(&As[row * AS_LD + c4 * 4]) = a;
            int kk = idx >> 5, wc4 = idx & 31;
            float4 wv = wrg[p];
            wv.x = rtf(wv.x); wv.y = rtf(wv.y); wv.z = rtf(wv.z); wv.w = rtf(wv.w);
            *reinterpret_cast<float4*>(&Ws[kk * WS_LD + wc4 * 4]) = wv;
        }
        __syncthreads();

        if (kt + 1 < niter) {
            const int k0n = (kt + 1) * 32;
#pragma unroll
            for (int p = 0; p < 4; p++) {
                int idx = tid + 256 * p;
                int row = idx >> 3, c4 = idx & 7;
                ar[p] = *reinterpret_cast<const float4*>(
                    &A[(size_t)(m0 + row) * K + k0n + c4 * 4]);
                int kk = idx >> 5, wc4 = idx & 31;
                wrg[p] = *reinterpret_cast<const float4*>(
                    &W[(size_t)(k0n + kk) * N + n0 + wc4 * 4]);
            }
        }

#pragma unroll
        for (int ks = 0; ks < 4; ks++) {
            unsigned af[4][4];
#pragma unroll
            for (int mt = 0; mt < 4; mt++) {
                const float* ab = &As[(wm0 + mt * 16 + gid) * AS_LD + ks * 8 + tig];
                af[mt][0] = __float_as_uint(ab[0]);
                af[mt][1] = __float_as_uint(ab[8 * AS_LD]);
                af[mt][2] = __float_as_uint(ab[4]);
                af[mt][3] = __float_as_uint(ab[8 * AS_LD + 4]);
            }
            unsigned bf[4][2];
#pragma unroll
            for (int nt = 0; nt < 4; nt++) {
                const float* bb = &Ws[(ks * 8 + tig) * WS_LD + wn0 + nt * 8 + gid];
                bf[nt][0] = __float_as_uint(bb[0]);
                bf[nt][1] = __float_as_uint(bb[4 * WS_LD]);
            }
#pragma unroll
            for (int mt = 0; mt < 4; mt++)
#pragma unroll
                for (int nt = 0; nt < 4; nt++)
                    mma_tf32(acc[mt][nt], af[mt], bf[nt][0], bf[nt][1]);
        }
    }

#pragma unroll
    for (int mt = 0; mt < 4; mt++) {
#pragma unroll
        for (int half = 0; half < 2; half++) {
            const int m = m0 + wm0 + mt * 16 + gid + half * 8;
#pragma unroll
            for (int nt = 0; nt < 4; nt++) {
                const int n = n0 + wn0 + nt * 8 + 2 * tig;
                float2 v;
                v.x = acc[mt][nt][half * 2 + 0] + bias[n + 0];
                v.y = acc[mt][nt][half * 2 + 1] + bias[n + 1];
                if (bhtd) {
                    v.x = rtf(v.x * oscale);
                    v.y = rtf(v.y * oscale);
                    const int b = m >> 11, t = m & 2047;
                    const int h = n >> 6, d = n & 63;
                    *reinterpret_cast<float2*>(
                        &out[(((size_t)(b * HEADS + h) * T_SEQ + t) * DH) + d]) = v;
                } else {
                    *reinterpret_cast<float2*>(&out[(size_t)m * N + n]) = v;
                }
            }
        }
    }
}

// ---------------- tf32 tensor-core causal flash attention -------------------
// 2 blocks/SM: cp.async double-buffered K/V, no register staging, no rounding.
#define BQ 128
#define BK 64
#define KS_LD 68
#define VS_LD 72
#define PS_LD 68
#define K0_OFF 0
#define V0_OFF (64 * KS_LD)                       // 4352
#define K1_OFF (V0_OFF + 64 * VS_LD)              // 8960
#define V1_OFF (K1_OFF + 64 * KS_LD)              // 13312
#define PS_OFF (V1_OFF + 64 * VS_LD)              // 17920
#define ATTN_SMEM_FLOATS (PS_OFF + 128 * PS_LD)   // 26624
#define ATTN_SMEM_BYTES  (ATTN_SMEM_FLOATS * 4)   // 106496

__global__ void __launch_bounds__(256, 2) attn_kernel(float* __restrict__ ctx)
{
    extern __shared__ float sm[];
    float* Ps = sm + PS_OFF;

    const int tid  = threadIdx.x;
    const int lane = tid & 31;
    const int w    = tid >> 5;
    const int gid  = lane >> 2;
    const int tig  = lane & 3;

    const int bh = blockIdx.y;
    const int qi = gridDim.x - 1 - blockIdx.x;   // heavy blocks first
    const int q0 = qi * BQ;

    const float* qb = g_q + (size_t)bh * T_SEQ * DH;
    const float* kb = g_k + (size_t)bh * T_SEQ * DH;
    const float* vb = g_v + (size_t)bh * T_SEQ * DH;

    // ---- stage Q (already tf32-rounded + pre-scaled by GEMM) ----
#pragma unroll
    for (int p = 0; p < 8; p++) {
        int idx = tid + 256 * p;
        int row = idx >> 4, c4 = idx & 15;
        *reinterpret_cast<float4*>(&Ps[row * PS_LD + c4 * 4]) =
            *reinterpret_cast<const float4*>(&qb[(size_t)(q0 + row) * DH + c4 * 4]);
    }
    __syncthreads();

    const int arow = w * 16 + gid;
    unsigned qf[8][4];
#pragma unroll
    for (int s = 0; s < 8; s++) {
        const float* base = &Ps[arow * PS_LD + s * 8 + tig];
        qf[s][0] = __float_as_uint(base[0]);
        qf[s][1] = __float_as_uint(base[8 * PS_LD]);
        qf[s][2] = __float_as_uint(base[4]);
        qf[s][3] = __float_as_uint(base[8 * PS_LD + 4]);
    }

    float O[8][4];
#pragma unroll
    for (int nt = 0; nt < 8; nt++)
#pragma unroll
        for (int j = 0; j < 4; j++) O[nt][j] = 0.f;
    float mA = -1e30f, mB = -1e30f, lA = 0.f, lB = 0.f;

    // per-thread cp.async slice: 4 rows of K and V per stage
    const int crow = tid >> 4;          // 0..15
    const int cc4  = tid & 15;          // 0..15 -> 16B chunk
    const u32 smem_base = (u32)__cvta_generic_to_shared(sm);

    const int ntiles = 2 * qi + 2;

    // prologue: issue tiles 0 and 1
    {
#pragma unroll
        for (int p = 0; p < 4; p++) {
            int row = crow + p * 16;
            cp_async16(smem_base + (K0_OFF + row * KS_LD + cc4 * 4) * 4,
                       &kb[(size_t)row * DH + cc4 * 4]);
            cp_async16(smem_base + (V0_OFF + row * VS_LD + cc4 * 4) * 4,
                       &vb[(size_t)row * DH + cc4 * 4]);
        }
        cp_commit();
        if (ntiles > 1) {
#pragma unroll
            for (int p = 0; p < 4; p++) {
                int row = crow + p * 16;
                cp_async16(smem_base + (K1_OFF + row * KS_LD + cc4 * 4) * 4,
                           &kb[(size_t)(BK + row) * DH + cc4 * 4]);
                cp_async16(smem_base + (V1_OFF + row * VS_LD + cc4 * 4) * 4,
                           &vb[(size_t)(BK + row) * DH + cc4 * 4]);
            }
            cp_commit();
        }
    }

    for (int kt = 0; kt < ntiles; kt++) {
        const int k0 = kt * BK;
        if (kt + 2 <= ntiles) cp_wait1(); else cp_wait0();
        __syncthreads();

        float* Ks = sm + ((kt & 1) ? K1_OFF : K0_OFF);
        float* Vs = sm + ((kt & 1) ? V1_OFF : V0_OFF);

        // warps entirely above the diagonal skip compute
        if (k0 <= q0 + w * 16 + 15) {
            // ---- S = Q K^T ----
            float S[8][4];
#pragma unroll
            for (int nt = 0; nt < 8; nt++)
#pragma unroll
                for (int j = 0; j < 4; j++) S[nt][j] = 0.f;
#pragma unroll
            for (int s = 0; s < 8; s++) {
#pragma unroll
                for (int nt = 0; nt < 8; nt++) {
                    const float* bb = &Ks[(nt * 8 + gid) * KS_LD + s * 8 + tig];
                    mma_tf32(S[nt], qf[s], __float_as_uint(bb[0]),
                             __float_as_uint(bb[4]));
                }
            }

            const int rA = q0 + arow;
            const int rB = rA + 8;
            if (k0 + BK - 1 > rA) {
#pragma unroll
                for (int nt = 0; nt < 8; nt++) {
                    const int c0 = k0 + nt * 8 + 2 * tig;
                    if (c0     > rA) S[nt][0] = -1e30f;
                    if (c0 + 1 > rA) S[nt][1] = -1e30f;
                    if (c0     > rB) S[nt][2] = -1e30f;
                    if (c0 + 1 > rB) S[nt][3] = -1e30f;
                }
            }

            // ---- online softmax ----
            float mxA = -1e30f, mxB = -1e30f;
#pragma unroll
            for (int nt = 0; nt < 8; nt++) {
                mxA = fmaxf(mxA, fmaxf(S[nt][0], S[nt][1]));
                mxB = fmaxf(mxB, fmaxf(S[nt][2], S[nt][3]));
            }
            mxA = fmaxf(mxA, __shfl_xor_sync(0xffffffffu, mxA, 1));
            mxA = fmaxf(mxA, __shfl_xor_sync(0xffffffffu, mxA, 2));
            mxB = fmaxf(mxB, __shfl_xor_sync(0xffffffffu, mxB, 1));
            mxB = fmaxf(mxB, __shfl_xor_sync(0xffffffffu, mxB, 2));

            const float mnA = fmaxf(mA, mxA), mnB = fmaxf(mB, mxB);
            const float aA = __expf(mA - mnA), aB = __expf(mB - mnB);
            float sA = 0.f, sB = 0.f;
#pragma unroll
            for (int nt = 0; nt < 8; nt++) {
                S[nt][0] = __expf(S[nt][0] - mnA);
                S[nt][1] = __expf(S[nt][1] - mnA);
                S[nt][2] = __expf(S[nt][2] - mnB);
                S[nt][3] = __expf(S[nt][3] - mnB);
                sA += S[nt][0] + S[nt][1];
                sB += S[nt][2] + S[nt][3];
            }
            sA += __shfl_xor_sync(0xffffffffu, sA, 1);
            sA += __shfl_xor_sync(0xffffffffu, sA, 2);
            sB += __shfl_xor_sync(0xffffffffu, sB, 1);
            sB += __shfl_xor_sync(0xffffffffu, sB, 2);
            lA = lA * aA + sA;  lB = lB * aB + sB;
            mA = mnA;           mB = mnB;
#pragma unroll
            for (int nt = 0; nt < 8; nt++) {
                O[nt][0] *= aA; O[nt][1] *= aA;
                O[nt][2] *= aB; O[nt][3] *= aB;
            }

            // ---- P: C-frag -> smem (warp-private rows) -> A-frag ----
#pragma unroll
            for (int nt = 0; nt < 8; nt++) {
                *reinterpret_cast<float2*>(&Ps[arow * PS_LD + nt * 8 + 2 * tig]) =
                    make_float2(S[nt][0], S[nt][1]);
                *reinterpret_cast<float2*>(&Ps[(arow + 8) * PS_LD + nt * 8 + 2 * tig]) =
                    make_float2(S[nt][2], S[nt][3]);
            }
            __syncwarp();

            // ---- O += P V ----
#pragma unroll
            for (int s = 0; s < 8; s++) {
                unsigned pa[4];
                const float* pb = &Ps[arow * PS_LD + s * 8 + tig];
                pa[0] = __float_as_uint(pb[0]);
                pa[1] = __float_as_uint(pb[8 * PS_LD]);
                pa[2] = __float_as_uint(pb[4]);
                pa[3] = __float_as_uint(pb[8 * PS_LD + 4]);
#pragma unroll
                for (int nt = 0; nt < 8; nt++) {
                    const float* vv = &Vs[(s * 8 + tig) * VS_LD + nt * 8 + gid];
                    mma_tf32(O[nt], pa, __float_as_uint(vv[0]),
                             __float_as_uint(vv[4 * VS_LD]));
                }
            }
        }

        __syncthreads();
        // issue tile kt+2 into the buffer just consumed
        if (kt + 2 < ntiles) {
            const int kn = (kt + 2) * BK;
            const int koff = (kt & 1) ? K1_OFF : K0_OFF;
            const int voff = (kt & 1) ? V1_OFF : V0_OFF;
#pragma unroll
            for (int p = 0; p < 4; p++) {
                int row = crow + p * 16;
                cp_async16(smem_base + (koff + row * KS_LD + cc4 * 4) * 4,
                           &kb[(size_t)(kn + row) * DH + cc4 * 4]);
                cp_async16(smem_base + (voff + row * VS_LD + cc4 * 4) * 4,
                           &vb[(size_t)(kn + row) * DH + cc4 * 4]);
            }
            cp_commit();
        }
    }

    // ---- epilogue ----
    const float iA = 1.f / lA, iB = 1.f / lB;
    const int b = bh / HEADS, h = bh % HEADS;
    const size_t rowA = (size_t)(b * T_SEQ + q0 + arow) * CDIM + h * DH;
    const size_t rowB = rowA + (size_t)8 * CDIM;
#pragma unroll
    for (int nt = 0; nt < 8; nt++) {
        *reinterpret_cast<float2*>(&ctx[rowA + nt * 8 + 2 * tig]) =
            make_float2(O[nt][0] * iA, O[nt][1] * iA);
        *reinterpret_cast<float2*>(&ctx[rowB + nt * 8 + 2 * tig]) =
            make_float2(O[nt][2] * iB, O[nt][3] * iB);
    }
}

// ---------------- launch ----------------------------------------------------
extern "C" void kernel_launch(void* const* d_in, const int* in_sizes, int n_in,
                              void* d_out, int out_size)
{
    (void)in_sizes; (void)n_in; (void)out_size;
    const float* x  = (const float*)d_in[0];
    const float* Wq = (const float*)d_in[1];
    const float* bq = (const float*)d_in[2];
    const float* Wk = (const float*)d_in[3];
    const float* bk = (const float*)d_in[4];
    const float* Wv = (const float*)d_in[5];
    const float* bv = (const float*)d_in[6];
    const float* Wo = (const float*)d_in[7];
    const float* bo = (const float*)d_in[8];
    float* out = (float*)d_out;

    static float *qp = nullptr, *kp = nullptr, *vp = nullptr, *cp = nullptr;
    if (!qp) {
        cudaGetSymbolAddress((void**)&qp, g_q);
        cudaGetSymbolAddress((void**)&kp, g_k);
        cudaGetSymbolAddress((void**)&vp, g_v);
        cudaGetSymbolAddress((void**)&cp, g_ctx);
        cudaFuncSetAttribute(attn_kernel,
                             cudaFuncAttributeMaxDynamicSharedMemorySize,
                             ATTN_SMEM_BYTES);
    }

    dim3 gblk(256);
    dim3 ggrid(CDIM / 128, MROWS / 128);   // (3, 64)

    gemm_tf32_kernel<<<ggrid, gblk>>>(x, Wq, bq, qp, MROWS, CDIM, CDIM, 1, 0.125f);
    gemm_tf32_kernel<<<ggrid, gblk>>>(x, Wk, bk, kp, MROWS, CDIM, CDIM, 1, 1.0f);
    gemm_tf32_kernel<<<ggrid, gblk>>>(x, Wv, bv, vp, MROWS, CDIM, CDIM, 1, 1.0f);

    dim3 agrid(T_SEQ / BQ, BATCH * HEADS);   // (16, 24)
    attn_kernel<<<agrid, 256, ATTN_SMEM_BYTES>>>(cp);

    gemm_tf32_kernel<<<ggrid, gblk>>>(cp, Wo, bo, out, MROWS, CDIM, CDIM, 0, 1.0f);
}

// round 7
// speedup vs baseline: 14.5006x; 1.7127x over previous
#include <cuda_runtime.h>
#include <cuda_fp16.h>

// Problem constants
#define BATCH   4
#define T_SEQ   2048
#define CDIM    384
#define HEADS   6
#define DH      64
#define MROWS   (BATCH * T_SEQ)        // 8192

typedef unsigned int u32;

// ---------------- scratch (static device globals; no runtime allocation) ----
__device__ __half g_q[BATCH * HEADS * T_SEQ * DH];  // [B,H,T,D], pre-scaled 1/8
__device__ __half g_k[BATCH * HEADS * T_SEQ * DH];  // [B,H,T,D]
__device__ __half g_v[BATCH * HEADS * T_SEQ * DH];  // [B,H,T,D]
__device__ float  g_ctx[MROWS * CDIM];              // [B*T, C]

// ---------------- primitives ------------------------------------------------
__device__ __forceinline__ u32 pack_h2(float lo, float hi) {
    u32 r;
    asm("cvt.rn.f16x2.f32 %0, %1, %2;" : "=r"(r) : "f"(hi), "f"(lo));
    return r;
}

__device__ __forceinline__ void mma_f16(float c[4], const u32 a[4], u32 b0, u32 b1) {
    asm volatile(
        "mma.sync.aligned.m16n8k16.row.col.f32.f16.f16.f32 "
        "{%0,%1,%2,%3}, {%4,%5,%6,%7}, {%8,%9}, {%0,%1,%2,%3};\n"
        : "+f"(c[0]), "+f"(c[1]), "+f"(c[2]), "+f"(c[3])
        : "r"(a[0]), "r"(a[1]), "r"(a[2]), "r"(a[3]), "r"(b0), "r"(b1));
}

__device__ __forceinline__ void ldm_x4(u32& r0, u32& r1, u32& r2, u32& r3, u32 addr) {
    asm volatile("ldmatrix.sync.aligned.m8n8.x4.shared.b16 {%0,%1,%2,%3}, [%4];"
                 : "=r"(r0), "=r"(r1), "=r"(r2), "=r"(r3) : "r"(addr));
}
__device__ __forceinline__ void ldm_x4t(u32& r0, u32& r1, u32& r2, u32& r3, u32 addr) {
    asm volatile("ldmatrix.sync.aligned.m8n8.x4.trans.shared.b16 {%0,%1,%2,%3}, [%4];"
                 : "=r"(r0), "=r"(r1), "=r"(r2), "=r"(r3) : "r"(addr));
}

__device__ __forceinline__ void cp_async16(u32 saddr, const void* gptr) {
    asm volatile("cp.async.cg.shared.global [%0], [%1], 16;" :: "r"(saddr), "l"(gptr));
}
__device__ __forceinline__ void cp_commit() { asm volatile("cp.async.commit_group;"); }
__device__ __forceinline__ void cp_wait1()  { asm volatile("cp.async.wait_group 1;"); }
__device__ __forceinline__ void cp_wait0()  { asm volatile("cp.async.wait_group 0;"); }

// ---------------- fp16 tensor-core GEMM: out = A[M,K] @ W[K,N] + bias -------
// Block 128x128, BK=32, 8 warps (2M x 4N), warp tile 64x32, m16n8k16.
// bhtd==1: out is __half [B,H,T,D], value = h( (acc+bias)*oscale )
// bhtd==0: out is float  [M,N]
#define AS_LD 40    // halfs
#define WS_LD 136   // halfs
__global__ __launch_bounds__(256, 2) void gemm_f16_kernel(
    const float* __restrict__ A, const float* __restrict__ W,
    const float* __restrict__ bias, void* __restrict__ outp,
    int M, int N, int K, int bhtd, float oscale)
{
    __shared__ __half As[128 * AS_LD];   // [m][k]
    __shared__ __half Ws[32 * WS_LD];    // [k][n]

    const int tid  = threadIdx.x;
    const int lane = tid & 31;
    const int w    = tid >> 5;
    const int gid  = lane >> 2;
    const int tig  = lane & 3;
    const int wm0  = (w & 1) * 64;
    const int wn0  = (w >> 1) * 32;
    const int n0   = blockIdx.x * 128;
    const int m0   = blockIdx.y * 128;
    const u32 ws_base = (u32)__cvta_generic_to_shared(Ws);

    float acc[4][4][4];
#pragma unroll
    for (int mt = 0; mt < 4; mt++)
#pragma unroll
        for (int nt = 0; nt < 4; nt++)
#pragma unroll
            for (int j = 0; j < 4; j++) acc[mt][nt][j] = 0.f;

    float4 ar[4], wrg[4];
#pragma unroll
    for (int p = 0; p < 4; p++) {
        int idx = tid + 256 * p;
        int row = idx >> 3, c4 = idx & 7;
        ar[p] = *reinterpret_cast<const float4*>(&A[(size_t)(m0 + row) * K + c4 * 4]);
        int kk = idx >> 5, wc4 = idx & 31;
        wrg[p] = *reinterpret_cast<const float4*>(&W[(size_t)kk * N + n0 + wc4 * 4]);
    }

    const int niter = K / 32;
    for (int kt = 0; kt < niter; kt++) {
        __syncthreads();
#pragma unroll
        for (int p = 0; p < 4; p++) {
            int idx = tid + 256 * p;
            int row = idx >> 3, c4 = idx & 7;
            *reinterpret_cast<uint2*>(&As[row * AS_LD + c4 * 4]) =
                make_uint2(pack_h2(ar[p].x, ar[p].y), pack_h2(ar[p].z, ar[p].w));
            int kk = idx >> 5, wc4 = idx & 31;
            *reinterpret_cast<uint2*>(&Ws[kk * WS_LD + wc4 * 4]) =
                make_uint2(pack_h2(wrg[p].x, wrg[p].y), pack_h2(wrg[p].z, wrg[p].w));
        }
        __syncthreads();

        if (kt + 1 < niter) {
            const int k0n = (kt + 1) * 32;
#pragma unroll
            for (int p = 0; p < 4; p++) {
                int idx = tid + 256 * p;
                int row = idx >> 3, c4 = idx & 7;
                ar[p] = *reinterpret_cast<const float4*>(
                    &A[(size_t)(m0 + row) * K + k0n + c4 * 4]);
                int kk = idx >> 5, wc4 = idx & 31;
                wrg[p] = *reinterpret_cast<const float4*>(
                    &W[(size_t)(k0n + kk) * N + n0 + wc4 * 4]);
            }
        }

#pragma unroll
        for (int ks = 0; ks < 2; ks++) {
            u32 af[4][4];
#pragma unroll
            for (int mt = 0; mt < 4; mt++) {
                const __half* ab = &As[(wm0 + mt * 16 + gid) * AS_LD + ks * 16 + 2 * tig];
                af[mt][0] = *reinterpret_cast<const u32*>(ab);
                af[mt][1] = *reinterpret_cast<const u32*>(ab + 8 * AS_LD);
                af[mt][2] = *reinterpret_cast<const u32*>(ab + 8);
                af[mt][3] = *reinterpret_cast<const u32*>(ab + 8 * AS_LD + 8);
            }
            u32 b0[4], b1[4];
#pragma unroll
            for (int nb = 0; nb < 2; nb++) {
                u32 addr = ws_base +
                    ((16 * ks + (lane & 15)) * WS_LD + wn0 + 16 * nb + (lane >> 4) * 8) * 2;
                ldm_x4t(b0[2 * nb], b1[2 * nb], b0[2 * nb + 1], b1[2 * nb + 1], addr);
            }
#pragma unroll
            for (int mt = 0; mt < 4; mt++)
#pragma unroll
                for (int nt = 0; nt < 4; nt++)
                    mma_f16(acc[mt][nt], af[mt], b0[nt], b1[nt]);
        }
    }

#pragma unroll
    for (int mt = 0; mt < 4; mt++) {
#pragma unroll
        for (int half = 0; half < 2; half++) {
            const int m = m0 + wm0 + mt * 16 + gid + half * 8;
#pragma unroll
            for (int nt = 0; nt < 4; nt++) {
                const int n = n0 + wn0 + nt * 8 + 2 * tig;
                float vx = acc[mt][nt][half * 2 + 0] + bias[n + 0];
                float vy = acc[mt][nt][half * 2 + 1] + bias[n + 1];
                if (bhtd) {
                    const int b = m >> 11, t = m & 2047;
                    const int h = n >> 6, d = n & 63;
                    __half* oh = (__half*)outp;
                    *reinterpret_cast<u32*>(
                        &oh[(((size_t)(b * HEADS + h) * T_SEQ + t) * DH) + d]) =
                        pack_h2(vx * oscale, vy * oscale);
                } else {
                    float* of = (float*)outp;
                    *reinterpret_cast<float2*>(&of[(size_t)m * N + n]) =
                        make_float2(vx, vy);
                }
            }
        }
    }
}

// ---------------- fp16 tensor-core causal flash attention -------------------
// BQ=128 (8 warps x 16 rows), BK=64, m16n8k16, P stays in registers.
#define BQ 128
#define BK 64
#define KS_LD 72   // halfs
#define VS_LD 72

__global__ void __launch_bounds__(256, 2) attn_kernel(float* __restrict__ ctx)
{
    __shared__ __half Kbuf[2][BK * KS_LD];
    __shared__ __half Vbuf[2][BK * VS_LD];

    const int tid  = threadIdx.x;
    const int lane = tid & 31;
    const int w    = tid >> 5;
    const int gid  = lane >> 2;
    const int tig  = lane & 3;

    const int bh = blockIdx.y;
    const int qi = gridDim.x - 1 - blockIdx.x;   // heavy blocks first
    const int q0 = qi * BQ;

    const __half* qb = g_q + (size_t)bh * T_SEQ * DH;
    const __half* kb = g_k + (size_t)bh * T_SEQ * DH;
    const __half* vb = g_v + (size_t)bh * T_SEQ * DH;

    // ---- Q A-frags straight from gmem (once per block) ----
    const int arow = w * 16 + gid;
    u32 qf[4][4];
#pragma unroll
    for (int s = 0; s < 4; s++) {
        const __half* base = &qb[(size_t)(q0 + arow) * DH + s * 16 + 2 * tig];
        qf[s][0] = *reinterpret_cast<const u32*>(base);
        qf[s][1] = *reinterpret_cast<const u32*>(base + 8 * DH);
        qf[s][2] = *reinterpret_cast<const u32*>(base + 8);
        qf[s][3] = *reinterpret_cast<const u32*>(base + 8 * DH + 8);
    }

    float O[8][4];
#pragma unroll
    for (int nt = 0; nt < 8; nt++)
#pragma unroll
        for (int j = 0; j < 4; j++) O[nt][j] = 0.f;
    float mA = -1e30f, mB = -1e30f, lA = 0.f, lB = 0.f;

    const u32 kbase[2] = { (u32)__cvta_generic_to_shared(Kbuf[0]),
                           (u32)__cvta_generic_to_shared(Kbuf[1]) };
    const u32 vbase[2] = { (u32)__cvta_generic_to_shared(Vbuf[0]),
                           (u32)__cvta_generic_to_shared(Vbuf[1]) };

    // cp.async mapping: 512 16B-chunks per tensor per tile, 2 per thread
    const int ldrow = tid >> 3;          // 0..31 base row (+32 for p=1)
    const int ldc   = tid & 7;           // 16B chunk within row (8 halfs)

    const int ntiles = 2 * qi + 2;

    // prologue: tiles 0 and 1
#pragma unroll
    for (int buf = 0; buf < 2; buf++) {
#pragma unroll
        for (int p = 0; p < 2; p++) {
            int row = ldrow + p * 32;
            cp_async16(kbase[buf] + (row * KS_LD + ldc * 8) * 2,
                       &kb[(size_t)(buf * BK + row) * DH + ldc * 8]);
            cp_async16(vbase[buf] + (row * VS_LD + ldc * 8) * 2,
                       &vb[(size_t)(buf * BK + row) * DH + ldc * 8]);
        }
        cp_commit();
    }

    for (int kt = 0; kt < ntiles; kt++) {
        const int k0 = kt * BK;
        if (kt + 2 <= ntiles) cp_wait1(); else cp_wait0();
        __syncthreads();

        const int buf = kt & 1;

        if (k0 <= q0 + w * 16 + 15) {     // warp not entirely above diagonal
            // ---- S = Q K^T : B-frags via ldmatrix (non-trans) ----
            float S[8][4];
#pragma unroll
            for (int nt = 0; nt < 8; nt++)
#pragma unroll
                for (int j = 0; j < 4; j++) S[nt][j] = 0.f;
#pragma unroll
            for (int s = 0; s < 4; s++) {
#pragma unroll
                for (int p = 0; p < 4; p++) {
                    u32 r0, r1, r2, r3;
                    u32 addr = kbase[buf] +
                        (((16 * p + (lane & 15)) * KS_LD) + 16 * s + (lane >> 4) * 8) * 2;
                    ldm_x4(r0, r1, r2, r3, addr);
                    mma_f16(S[2 * p],     qf[s], r0, r2);
                    mma_f16(S[2 * p + 1], qf[s], r1, r3);
                }
            }

            // ---- causal mask ----
            const int rA = q0 + arow;
            const int rB = rA + 8;
            if (k0 + BK - 1 > rA) {
#pragma unroll
                for (int nt = 0; nt < 8; nt++) {
                    const int c0 = k0 + nt * 8 + 2 * tig;
                    if (c0     > rA) S[nt][0] = -1e30f;
                    if (c0 + 1 > rA) S[nt][1] = -1e30f;
                    if (c0     > rB) S[nt][2] = -1e30f;
                    if (c0 + 1 > rB) S[nt][3] = -1e30f;
                }
            }

            // ---- online softmax ----
            float mxA = -1e30f, mxB = -1e30f;
#pragma unroll
            for (int nt = 0; nt < 8; nt++) {
                mxA = fmaxf(mxA, fmaxf(S[nt][0], S[nt][1]));
                mxB = fmaxf(mxB, fmaxf(S[nt][2], S[nt][3]));
            }
            mxA = fmaxf(mxA, __shfl_xor_sync(0xffffffffu, mxA, 1));
            mxA = fmaxf(mxA, __shfl_xor_sync(0xffffffffu, mxA, 2));
            mxB = fmaxf(mxB, __shfl_xor_sync(0xffffffffu, mxB, 1));
            mxB = fmaxf(mxB, __shfl_xor_sync(0xffffffffu, mxB, 2));

            const float mnA = fmaxf(mA, mxA), mnB = fmaxf(mB, mxB);
            const float aA = __expf(mA - mnA), aB = __expf(mB - mnB);
            float sA = 0.f, sB = 0.f;
#pragma unroll
            for (int nt = 0; nt < 8; nt++) {
                S[nt][0] = __expf(S[nt][0] - mnA);
                S[nt][1] = __expf(S[nt][1] - mnA);
                S[nt][2] = __expf(S[nt][2] - mnB);
                S[nt][3] = __expf(S[nt][3] - mnB);
                sA += S[nt][0] + S[nt][1];
                sB += S[nt][2] + S[nt][3];
            }
            sA += __shfl_xor_sync(0xffffffffu, sA, 1);
            sA += __shfl_xor_sync(0xffffffffu, sA, 2);
            sB += __shfl_xor_sync(0xffffffffu, sB, 1);
            sB += __shfl_xor_sync(0xffffffffu, sB, 2);
            lA = lA * aA + sA;  lB = lB * aB + sB;
            mA = mnA;           mB = mnB;
#pragma unroll
            for (int nt = 0; nt < 8; nt++) {
                O[nt][0] *= aA; O[nt][1] *= aA;
                O[nt][2] *= aB; O[nt][3] *= aB;
            }

            // ---- P: C-frag -> A-frag in registers (no smem) ----
            u32 pa[4][4];
#pragma unroll
            for (int s2 = 0; s2 < 4; s2++) {
                pa[s2][0] = pack_h2(S[2 * s2][0],     S[2 * s2][1]);
                pa[s2][1] = pack_h2(S[2 * s2][2],     S[2 * s2][3]);
                pa[s2][2] = pack_h2(S[2 * s2 + 1][0], S[2 * s2 + 1][1]);
                pa[s2][3] = pack_h2(S[2 * s2 + 1][2], S[2 * s2 + 1][3]);
            }

            // ---- O += P V : B-frags via ldmatrix.trans ----
#pragma unroll
            for (int s2 = 0; s2 < 4; s2++) {
#pragma unroll
                for (int nb = 0; nb < 4; nb++) {
                    u32 r0, r1, r2, r3;
                    u32 addr = vbase[buf] +
                        (((16 * s2 + (lane & 15)) * VS_LD) + 16 * nb + (lane >> 4) * 8) * 2;
                    ldm_x4t(r0, r1, r2, r3, addr);
                    mma_f16(O[2 * nb],     pa[s2], r0, r1);
                    mma_f16(O[2 * nb + 1], pa[s2], r2, r3);
                }
            }
        }

        __syncthreads();
        // refill the buffer just consumed with tile kt+2
        if (kt + 2 < ntiles) {
            const int kn = (kt + 2) * BK;
#pragma unroll
            for (int p = 0; p < 2; p++) {
                int row = ldrow + p * 32;
                cp_async16(kbase[buf] + (row * KS_LD + ldc * 8) * 2,
                           &kb[(size_t)(kn + row) * DH + ldc * 8]);
                cp_async16(vbase[buf] + (row * VS_LD + ldc * 8) * 2,
                           &vb[(size_t)(kn + row) * DH + ldc * 8]);
            }
            cp_commit();
        }
    }

    // ---- epilogue ----
    const float iA = 1.f / lA, iB = 1.f / lB;
    const int b = bh / HEADS, h = bh % HEADS;
    const size_t rowA = (size_t)(b * T_SEQ + q0 + arow) * CDIM + h * DH;
    const size_t rowB = rowA + (size_t)8 * CDIM;
#pragma unroll
    for (int nt = 0; nt < 8; nt++) {
        *reinterpret_cast<float2*>(&ctx[rowA + nt * 8 + 2 * tig]) =
            make_float2(O[nt][0] * iA, O[nt][1] * iA);
        *reinterpret_cast<float2*>(&ctx[rowB + nt * 8 + 2 * tig]) =
            make_float2(O[nt][2] * iB, O[nt][3] * iB);
    }
}

// ---------------- launch ----------------------------------------------------
extern "C" void kernel_launch(void* const* d_in, const int* in_sizes, int n_in,
                              void* d_out, int out_size)
{
    (void)in_sizes; (void)n_in; (void)out_size;
    const float* x  = (const float*)d_in[0];
    const float* Wq = (const float*)d_in[1];
    const float* bq = (const float*)d_in[2];
    const float* Wk = (const float*)d_in[3];
    const float* bk = (const float*)d_in[4];
    const float* Wv = (const float*)d_in[5];
    const float* bv = (const float*)d_in[6];
    const float* Wo = (const float*)d_in[7];
    const float* bo = (const float*)d_in[8];
    float* out = (float*)d_out;

    static void *qp = nullptr, *kp = nullptr, *vp = nullptr;
    static float* cp = nullptr;
    if (!qp) {
        cudaGetSymbolAddress(&qp, g_q);
        cudaGetSymbolAddress(&kp, g_k);
        cudaGetSymbolAddress(&vp, g_v);
        cudaGetSymbolAddress((void**)&cp, g_ctx);
    }

    dim3 gblk(256);
    dim3 ggrid(CDIM / 128, MROWS / 128);   // (3, 64)

    gemm_f16_kernel<<<ggrid, gblk>>>(x, Wq, bq, qp, MROWS, CDIM, CDIM, 1, 0.125f);
    gemm_f16_kernel<<<ggrid, gblk>>>(x, Wk, bk, kp, MROWS, CDIM, CDIM, 1, 1.0f);
    gemm_f16_kernel<<<ggrid, gblk>>>(x, Wv, bv, vp, MROWS, CDIM, CDIM, 1, 1.0f);

    dim3 agrid(T_SEQ / BQ, BATCH * HEADS);   // (16, 24)
    attn_kernel<<<agrid, 256>>>(cp);

    gemm_f16_kernel<<<ggrid, gblk>>>(cp, Wo, bo, out, MROWS, CDIM, CDIM, 0, 1.0f);
}

// round 8
// speedup vs baseline: 17.0752x; 1.1776x over previous
#include <cuda_runtime.h>
#include <cuda_fp16.h>

// Problem constants
#define BATCH   4
#define T_SEQ   2048
#define CDIM    384
#define HEADS   6
#define DH      64
#define MROWS   (BATCH * T_SEQ)        // 8192

typedef unsigned int u32;

// Q pre-scale: 1/sqrt(64) * log2(e)  (base-2 softmax)
#define QSCALE (0.125f * 1.4426950408889634f)

// ---------------- scratch (static device globals; no runtime allocation) ----
__device__ __half g_q[BATCH * HEADS * T_SEQ * DH];  // [B,H,T,D], pre-scaled
__device__ __half g_k[BATCH * HEADS * T_SEQ * DH];  // [B,H,T,D]
__device__ __half g_v[BATCH * HEADS * T_SEQ * DH];  // [B,H,T,D]
__device__ float  g_ctx[MROWS * CDIM];              // [B*T, C]

// ---------------- primitives ------------------------------------------------
__device__ __forceinline__ u32 pack_h2(float lo, float hi) {
    u32 r;
    asm("cvt.rn.f16x2.f32 %0, %1, %2;" : "=r"(r) : "f"(hi), "f"(lo));
    return r;
}

__device__ __forceinline__ void mma_f16(float c[4], const u32 a[4], u32 b0, u32 b1) {
    asm volatile(
        "mma.sync.aligned.m16n8k16.row.col.f32.f16.f16.f32 "
        "{%0,%1,%2,%3}, {%4,%5,%6,%7}, {%8,%9}, {%0,%1,%2,%3};\n"
        : "+f"(c[0]), "+f"(c[1]), "+f"(c[2]), "+f"(c[3])
        : "r"(a[0]), "r"(a[1]), "r"(a[2]), "r"(a[3]), "r"(b0), "r"(b1));
}

__device__ __forceinline__ void ldm_x4(u32& r0, u32& r1, u32& r2, u32& r3, u32 addr) {
    asm volatile("ldmatrix.sync.aligned.m8n8.x4.shared.b16 {%0,%1,%2,%3}, [%4];"
                 : "=r"(r0), "=r"(r1), "=r"(r2), "=r"(r3) : "r"(addr));
}
__device__ __forceinline__ void ldm_x4t(u32& r0, u32& r1, u32& r2, u32& r3, u32 addr) {
    asm volatile("ldmatrix.sync.aligned.m8n8.x4.trans.shared.b16 {%0,%1,%2,%3}, [%4];"
                 : "=r"(r0), "=r"(r1), "=r"(r2), "=r"(r3) : "r"(addr));
}

__device__ __forceinline__ void cp_async16(u32 saddr, const void* gptr) {
    asm volatile("cp.async.cg.shared.global [%0], [%1], 16;" :: "r"(saddr), "l"(gptr));
}
__device__ __forceinline__ void cp_commit() { asm volatile("cp.async.commit_group;"); }
__device__ __forceinline__ void cp_wait1()  { asm volatile("cp.async.wait_group 1;"); }
__device__ __forceinline__ void cp_wait0()  { asm volatile("cp.async.wait_group 0;"); }

// ---------------- shared GEMM core (fp16 mma, 128x128 tile, BK=32) ----------
#define AS_LD 40    // halfs
#define WS_LD 136   // halfs

struct GemmCoreOut {
    float acc[4][4][4];
    int wm0, wn0;
};

template <typename EPI>
__device__ __forceinline__ void gemm_core_f16(
    const float* __restrict__ A, const float* __restrict__ W,
    int K, int N, int m0, int n0, __half* As, __half* Ws, EPI epi)
{
    const int tid  = threadIdx.x;
    const int lane = tid & 31;
    const int w    = tid >> 5;
    const int gid  = lane >> 2;
    const int tig  = lane & 3;
    const int wm0  = (w & 1) * 64;
    const int wn0  = (w >> 1) * 32;
    const u32 ws_base = (u32)__cvta_generic_to_shared(Ws);

    float acc[4][4][4];
#pragma unroll
    for (int mt = 0; mt < 4; mt++)
#pragma unroll
        for (int nt = 0; nt < 4; nt++)
#pragma unroll
            for (int j = 0; j < 4; j++) acc[mt][nt][j] = 0.f;

    float4 ar[4], wrg[4];
#pragma unroll
    for (int p = 0; p < 4; p++) {
        int idx = tid + 256 * p;
        int row = idx >> 3, c4 = idx & 7;
        ar[p] = *reinterpret_cast<const float4*>(&A[(size_t)(m0 + row) * K + c4 * 4]);
        int kk = idx >> 5, wc4 = idx & 31;
        wrg[p] = *reinterpret_cast<const float4*>(&W[(size_t)kk * N + n0 + wc4 * 4]);
    }

    const int niter = K / 32;
    for (int kt = 0; kt < niter; kt++) {
        __syncthreads();
#pragma unroll
        for (int p = 0; p < 4; p++) {
            int idx = tid + 256 * p;
            int row = idx >> 3, c4 = idx & 7;
            *reinterpret_cast<uint2*>(&As[row * AS_LD + c4 * 4]) =
                make_uint2(pack_h2(ar[p].x, ar[p].y), pack_h2(ar[p].z, ar[p].w));
            int kk = idx >> 5, wc4 = idx & 31;
            *reinterpret_cast<uint2*>(&Ws[kk * WS_LD + wc4 * 4]) =
                make_uint2(pack_h2(wrg[p].x, wrg[p].y), pack_h2(wrg[p].z, wrg[p].w));
        }
        __syncthreads();

        if (kt + 1 < niter) {
            const int k0n = (kt + 1) * 32;
#pragma unroll
            for (int p = 0; p < 4; p++) {
                int idx = tid + 256 * p;
                int row = idx >> 3, c4 = idx & 7;
                ar[p] = *reinterpret_cast<const float4*>(
                    &A[(size_t)(m0 + row) * K + k0n + c4 * 4]);
                int kk = idx >> 5, wc4 = idx & 31;
                wrg[p] = *reinterpret_cast<const float4*>(
                    &W[(size_t)(k0n + kk) * N + n0 + wc4 * 4]);
            }
        }

#pragma unroll
        for (int ks = 0; ks < 2; ks++) {
            u32 af[4][4];
#pragma unroll
            for (int mt = 0; mt < 4; mt++) {
                const __half* ab = &As[(wm0 + mt * 16 + gid) * AS_LD + ks * 16 + 2 * tig];
                af[mt][0] = *reinterpret_cast<const u32*>(ab);
                af[mt][1] = *reinterpret_cast<const u32*>(ab + 8 * AS_LD);
                af[mt][2] = *reinterpret_cast<const u32*>(ab + 8);
                af[mt][3] = *reinterpret_cast<const u32*>(ab + 8 * AS_LD + 8);
            }
            u32 b0[4], b1[4];
#pragma unroll
            for (int nb = 0; nb < 2; nb++) {
                u32 addr = ws_base +
                    ((16 * ks + (lane & 15)) * WS_LD + wn0 + 16 * nb + (lane >> 4) * 8) * 2;
                ldm_x4t(b0[2 * nb], b1[2 * nb], b0[2 * nb + 1], b1[2 * nb + 1], addr);
            }
#pragma unroll
            for (int mt = 0; mt < 4; mt++)
#pragma unroll
                for (int nt = 0; nt < 4; nt++)
                    mma_f16(acc[mt][nt], af[mt], b0[nt], b1[nt]);
        }
    }
    epi(acc, wm0, wn0, gid, tig);
}

// ---------------- merged QKV projection (one launch, grid 9 x 64) -----------
__global__ __launch_bounds__(256, 2) void gemm_qkv_kernel(
    const float* __restrict__ x,
    const float* __restrict__ Wq, const float* __restrict__ bq,
    const float* __restrict__ Wk, const float* __restrict__ bk,
    const float* __restrict__ Wv, const float* __restrict__ bv,
    __half* __restrict__ qp, __half* __restrict__ kp, __half* __restrict__ vp)
{
    __shared__ __half As[128 * AS_LD];
    __shared__ __half Ws[32 * WS_LD];

    const int sel = blockIdx.x / 3;
    const int n0  = (blockIdx.x % 3) * 128;
    const int m0  = blockIdx.y * 128;
    const float* W    = (sel == 0) ? Wq : ((sel == 1) ? Wk : Wv);
    const float* bias = (sel == 0) ? bq : ((sel == 1) ? bk : bv);
    __half* out       = (sel == 0) ? qp : ((sel == 1) ? kp : vp);
    const float oscale = (sel == 0) ? QSCALE : 1.0f;

    gemm_core_f16(x, W, CDIM, CDIM, m0, n0, As, Ws,
        [&](float acc[4][4][4], int wm0, int wn0, int gid, int tig) {
#pragma unroll
            for (int mt = 0; mt < 4; mt++) {
#pragma unroll
                for (int half = 0; half < 2; half++) {
                    const int m = m0 + wm0 + mt * 16 + gid + half * 8;
#pragma unroll
                    for (int nt = 0; nt < 4; nt++) {
                        const int n = n0 + wn0 + nt * 8 + 2 * tig;
                        float vx = (acc[mt][nt][half * 2 + 0] + bias[n + 0]) * oscale;
                        float vy = (acc[mt][nt][half * 2 + 1] + bias[n + 1]) * oscale;
                        const int b = m >> 11, t = m & 2047;
                        const int h = n >> 6, d = n & 63;
                        *reinterpret_cast<u32*>(
                            &out[(((size_t)(b * HEADS + h) * T_SEQ + t) * DH) + d]) =
                            pack_h2(vx, vy);
                    }
                }
            }
        });
}

// ---------------- output projection: float out [M,N] ------------------------
__global__ __launch_bounds__(256, 2) void gemm_out_kernel(
    const float* __restrict__ A, const float* __restrict__ W,
    const float* __restrict__ bias, float* __restrict__ out)
{
    __shared__ __half As[128 * AS_LD];
    __shared__ __half Ws[32 * WS_LD];
    const int n0 = blockIdx.x * 128;
    const int m0 = blockIdx.y * 128;

    gemm_core_f16(A, W, CDIM, CDIM, m0, n0, As, Ws,
        [&](float acc[4][4][4], int wm0, int wn0, int gid, int tig) {
#pragma unroll
            for (int mt = 0; mt < 4; mt++) {
#pragma unroll
                for (int half = 0; half < 2; half++) {
                    const int m = m0 + wm0 + mt * 16 + gid + half * 8;
#pragma unroll
                    for (int nt = 0; nt < 4; nt++) {
                        const int n = n0 + wn0 + nt * 8 + 2 * tig;
                        *reinterpret_cast<float2*>(&out[(size_t)m * CDIM + n]) =
                            make_float2(acc[mt][nt][half * 2 + 0] + bias[n + 0],
                                        acc[mt][nt][half * 2 + 1] + bias[n + 1]);
                    }
                }
            }
        });
}

// ---------------- fp16 tensor-core causal flash attention -------------------
// BQ=128 (8 warps x 16 rows), BK=64, m16n8k16, P in registers, base-2 softmax.
#define BQ 128
#define BK 64
#define KS_LD 72   // halfs
#define VS_LD 72

__global__ void __launch_bounds__(256, 2) attn_kernel(float* __restrict__ ctx)
{
    __shared__ __half Kbuf[2][BK * KS_LD];
    __shared__ __half Vbuf[2][BK * VS_LD];

    const int tid  = threadIdx.x;
    const int lane = tid & 31;
    const int w    = tid >> 5;
    const int gid  = lane >> 2;
    const int tig  = lane & 3;

    const int bh = blockIdx.y;
    const int qi = gridDim.x - 1 - blockIdx.x;   // heavy blocks first
    const int q0 = qi * BQ;

    const __half* qb = g_q + (size_t)bh * T_SEQ * DH;
    const __half* kb = g_k + (size_t)bh * T_SEQ * DH;
    const __half* vb = g_v + (size_t)bh * T_SEQ * DH;

    // ---- Q A-frags straight from gmem (once per block) ----
    const int arow = w * 16 + gid;
    u32 qf[4][4];
#pragma unroll
    for (int s = 0; s < 4; s++) {
        const __half* base = &qb[(size_t)(q0 + arow) * DH + s * 16 + 2 * tig];
        qf[s][0] = *reinterpret_cast<const u32*>(base);
        qf[s][1] = *reinterpret_cast<const u32*>(base + 8 * DH);
        qf[s][2] = *reinterpret_cast<const u32*>(base + 8);
        qf[s][3] = *reinterpret_cast<const u32*>(base + 8 * DH + 8);
    }

    float O[8][4];
#pragma unroll
    for (int nt = 0; nt < 8; nt++)
#pragma unroll
        for (int j = 0; j < 4; j++) O[nt][j] = 0.f;
    float mA = -1e30f, mB = -1e30f, lA = 0.f, lB = 0.f;

    const u32 kbase[2] = { (u32)__cvta_generic_to_shared(Kbuf[0]),
                           (u32)__cvta_generic_to_shared(Kbuf[1]) };
    const u32 vbase[2] = { (u32)__cvta_generic_to_shared(Vbuf[0]),
                           (u32)__cvta_generic_to_shared(Vbuf[1]) };

    const int ldrow = tid >> 3;          // 0..31 base row (+32 for p=1)
    const int ldc   = tid & 7;           // 16B chunk within row (8 halfs)

    const int ntiles = 2 * qi + 2;

    // prologue: tiles 0 and 1
#pragma unroll
    for (int buf = 0; buf < 2; buf++) {
#pragma unroll
        for (int p = 0; p < 2; p++) {
            int row = ldrow + p * 32;
            cp_async16(kbase[buf] + (row * KS_LD + ldc * 8) * 2,
                       &kb[(size_t)(buf * BK + row) * DH + ldc * 8]);
            cp_async16(vbase[buf] + (row * VS_LD + ldc * 8) * 2,
                       &vb[(size_t)(buf * BK + row) * DH + ldc * 8]);
        }
        cp_commit();
    }

    for (int kt = 0; kt < ntiles; kt++) {
        const int k0 = kt * BK;
        if (kt + 2 <= ntiles) cp_wait1(); else cp_wait0();
        __syncthreads();

        const int buf = kt & 1;

        if (k0 <= q0 + w * 16 + 15) {     // warp not entirely above diagonal
            // ---- S = Q K^T ----
            float S[8][4];
#pragma unroll
            for (int nt = 0; nt < 8; nt++)
#pragma unroll
                for (int j = 0; j < 4; j++) S[nt][j] = 0.f;
#pragma unroll
            for (int s = 0; s < 4; s++) {
#pragma unroll
                for (int p = 0; p < 4; p++) {
                    u32 r0, r1, r2, r3;
                    u32 addr = kbase[buf] +
                        (((16 * p + (lane & 15)) * KS_LD) + 16 * s + (lane >> 4) * 8) * 2;
                    ldm_x4(r0, r1, r2, r3, addr);
                    mma_f16(S[2 * p],     qf[s], r0, r2);
                    mma_f16(S[2 * p + 1], qf[s], r1, r3);
                }
            }

            // ---- causal mask ----
            const int rA = q0 + arow;
            const int rB = rA + 8;
            if (k0 + BK - 1 > rA) {
#pragma unroll
                for (int nt = 0; nt < 8; nt++) {
                    const int c0 = k0 + nt * 8 + 2 * tig;
                    if (c0     > rA) S[nt][0] = -1e30f;
                    if (c0 + 1 > rA) S[nt][1] = -1e30f;
                    if (c0     > rB) S[nt][2] = -1e30f;
                    if (c0 + 1 > rB) S[nt][3] = -1e30f;
                }
            }

            // ---- online softmax (base 2; Q pre-scaled by log2e) ----
            float mxA = -1e30f, mxB = -1e30f;
#pragma unroll
            for (int nt = 0; nt < 8; nt++) {
                mxA = fmaxf(mxA, fmaxf(S[nt][0], S[nt][1]));
                mxB = fmaxf(mxB, fmaxf(S[nt][2], S[nt][3]));
            }
            mxA = fmaxf(mxA, __shfl_xor_sync(0xffffffffu, mxA, 1));
            mxA = fmaxf(mxA, __shfl_xor_sync(0xffffffffu, mxA, 2));
            mxB = fmaxf(mxB, __shfl_xor_sync(0xffffffffu, mxB, 1));
            mxB = fmaxf(mxB, __shfl_xor_sync(0xffffffffu, mxB, 2));

            const float mnA = fmaxf(mA, mxA), mnB = fmaxf(mB, mxB);
            const float aA = exp2f(mA - mnA), aB = exp2f(mB - mnB);
            float sA = 0.f, sB = 0.f;
#pragma unroll
            for (int nt = 0; nt < 8; nt++) {
                S[nt][0] = exp2f(S[nt][0] - mnA);
                S[nt][1] = exp2f(S[nt][1] - mnA);
                S[nt][2] = exp2f(S[nt][2] - mnB);
                S[nt][3] = exp2f(S[nt][3] - mnB);
                sA += S[nt][0] + S[nt][1];
                sB += S[nt][2] + S[nt][3];
            }
            sA += __shfl_xor_sync(0xffffffffu, sA, 1);
            sA += __shfl_xor_sync(0xffffffffu, sA, 2);
            sB += __shfl_xor_sync(0xffffffffu, sB, 1);
            sB += __shfl_xor_sync(0xffffffffu, sB, 2);
            lA = lA * aA + sA;  lB = lB * aB + sB;
            mA = mnA;           mB = mnB;
#pragma unroll
            for (int nt = 0; nt < 8; nt++) {
                O[nt][0] *= aA; O[nt][1] *= aA;
                O[nt][2] *= aB; O[nt][3] *= aB;
            }

            // ---- P: C-frag -> A-frag in registers ----
            u32 pa[4][4];
#pragma unroll
            for (int s2 = 0; s2 < 4; s2++) {
                pa[s2][0] = pack_h2(S[2 * s2][0],     S[2 * s2][1]);
                pa[s2][1] = pack_h2(S[2 * s2][2],     S[2 * s2][3]);
                pa[s2][2] = pack_h2(S[2 * s2 + 1][0], S[2 * s2 + 1][1]);
                pa[s2][3] = pack_h2(S[2 * s2 + 1][2], S[2 * s2 + 1][3]);
            }

            // ---- O += P V ----
#pragma unroll
            for (int s2 = 0; s2 < 4; s2++) {
#pragma unroll
                for (int nb = 0; nb < 4; nb++) {
                    u32 r0, r1, r2, r3;
                    u32 addr = vbase[buf] +
                        (((16 * s2 + (lane & 15)) * VS_LD) + 16 * nb + (lane >> 4) * 8) * 2;
                    ldm_x4t(r0, r1, r2, r3, addr);
                    mma_f16(O[2 * nb],     pa[s2], r0, r1);
                    mma_f16(O[2 * nb + 1], pa[s2], r2, r3);
                }
            }
        }

        __syncthreads();
        if (kt + 2 < ntiles) {
            const int kn = (kt + 2) * BK;
#pragma unroll
            for (int p = 0; p < 2; p++) {
                int row = ldrow + p * 32;
                cp_async16(kbase[buf] + (row * KS_LD + ldc * 8) * 2,
                           &kb[(size_t)(kn + row) * DH + ldc * 8]);
                cp_async16(vbase[buf] + (row * VS_LD + ldc * 8) * 2,
                           &vb[(size_t)(kn + row) * DH + ldc * 8]);
            }
            cp_commit();
        }
    }

    // ---- epilogue ----
    const float iA = 1.f / lA, iB = 1.f / lB;
    const int b = bh / HEADS, h = bh % HEADS;
    const size_t rowA = (size_t)(b * T_SEQ + q0 + arow) * CDIM + h * DH;
    const size_t rowB = rowA + (size_t)8 * CDIM;
#pragma unroll
    for (int nt = 0; nt < 8; nt++) {
        *reinterpret_cast<float2*>(&ctx[rowA + nt * 8 + 2 * tig]) =
            make_float2(O[nt][0] * iA, O[nt][1] * iA);
        *reinterpret_cast<float2*>(&ctx[rowB + nt * 8 + 2 * tig]) =
            make_float2(O[nt][2] * iB, O[nt][3] * iB);
    }
}

// ---------------- launch ----------------------------------------------------
extern "C" void kernel_launch(void* const* d_in, const int* in_sizes, int n_in,
                              void* d_out, int out_size)
{
    (void)in_sizes; (void)n_in; (void)out_size;
    const float* x  = (const float*)d_in[0];
    const float* Wq = (const float*)d_in[1];
    const float* bq = (const float*)d_in[2];
    const float* Wk = (const float*)d_in[3];
    const float* bk = (const float*)d_in[4];
    const float* Wv = (const float*)d_in[5];
    const float* bv = (const float*)d_in[6];
    const float* Wo = (const float*)d_in[7];
    const float* bo = (const float*)d_in[8];
    float* out = (float*)d_out;

    static __half *qp = nullptr, *kp = nullptr, *vp = nullptr;
    static float* cp = nullptr;
    if (!qp) {
        cudaGetSymbolAddress((void**)&qp, g_q);
        cudaGetSymbolAddress((void**)&kp, g_k);
        cudaGetSymbolAddress((void**)&vp, g_v);
        cudaGetSymbolAddress((void**)&cp, g_ctx);
    }

    dim3 gblk(256);

    // merged QKV projection: grid (9, 64)
    dim3 qkvgrid(9, MROWS / 128);
    gemm_qkv_kernel<<<qkvgrid, gblk>>>(x, Wq, bq, Wk, bk, Wv, bv, qp, kp, vp);

    dim3 agrid(T_SEQ / BQ, BATCH * HEADS);   // (16, 24)
    attn_kernel<<<agrid, 256>>>(cp);

    dim3 ogrid(CDIM / 128, MROWS / 128);     // (3, 64)
    gemm_out_kernel<<<ogrid, gblk>>>(cp, Wo, bo, out);
}

// round 9
// speedup vs baseline: 17.8641x; 1.0462x over previous
#include <cuda_runtime.h>
#include <cuda_fp16.h>

// Problem constants
#define BATCH   4
#define T_SEQ   2048
#define CDIM    384
#define HEADS   6
#define DH      64
#define MROWS   (BATCH * T_SEQ)        // 8192

typedef unsigned int u32;

// Q pre-scale: 1/sqrt(64) * log2(e)  (base-2 softmax)
#define QSCALE (0.125f * 1.4426950408889634f)
#define ONES_H2 0x3C003C00u            // fp16 {1.0, 1.0}

// ---------------- scratch (static device globals; no runtime allocation) ----
__device__ __half g_q[BATCH * HEADS * T_SEQ * DH];  // [B,H,T,D], pre-scaled
__device__ __half g_k[BATCH * HEADS * T_SEQ * DH];  // [B,H,T,D]
__device__ __half g_v[BATCH * HEADS * T_SEQ * DH];  // [B,H,T,D]
__device__ float  g_ctx[MROWS * CDIM];              // [B*T, C]

// ---------------- primitives ------------------------------------------------
__device__ __forceinline__ u32 pack_h2(float lo, float hi) {
    u32 r;
    asm("cvt.rn.f16x2.f32 %0, %1, %2;" : "=r"(r) : "f"(hi), "f"(lo));
    return r;
}
__device__ __forceinline__ float ex2f(float x) {
    float y;
    asm("ex2.approx.f32 %0, %1;" : "=f"(y) : "f"(x));
    return y;
}

__device__ __forceinline__ void mma_f16(float c[4], const u32 a[4], u32 b0, u32 b1) {
    asm volatile(
        "mma.sync.aligned.m16n8k16.row.col.f32.f16.f16.f32 "
        "{%0,%1,%2,%3}, {%4,%5,%6,%7}, {%8,%9}, {%0,%1,%2,%3};\n"
        : "+f"(c[0]), "+f"(c[1]), "+f"(c[2]), "+f"(c[3])
        : "r"(a[0]), "r"(a[1]), "r"(a[2]), "r"(a[3]), "r"(b0), "r"(b1));
}

__device__ __forceinline__ void ldm_x4(u32& r0, u32& r1, u32& r2, u32& r3, u32 addr) {
    asm volatile("ldmatrix.sync.aligned.m8n8.x4.shared.b16 {%0,%1,%2,%3}, [%4];"
                 : "=r"(r0), "=r"(r1), "=r"(r2), "=r"(r3) : "r"(addr));
}
__device__ __forceinline__ void ldm_x4t(u32& r0, u32& r1, u32& r2, u32& r3, u32 addr) {
    asm volatile("ldmatrix.sync.aligned.m8n8.x4.trans.shared.b16 {%0,%1,%2,%3}, [%4];"
                 : "=r"(r0), "=r"(r1), "=r"(r2), "=r"(r3) : "r"(addr));
}

__device__ __forceinline__ void cp_async16(u32 saddr, const void* gptr) {
    asm volatile("cp.async.cg.shared.global [%0], [%1], 16;" :: "r"(saddr), "l"(gptr));
}
__device__ __forceinline__ void cp_commit() { asm volatile("cp.async.commit_group;"); }
__device__ __forceinline__ void cp_wait1()  { asm volatile("cp.async.wait_group 1;"); }
__device__ __forceinline__ void cp_wait0()  { asm volatile("cp.async.wait_group 0;"); }

// ---------------- shared GEMM core (fp16 mma, 128x128 tile, BK=32) ----------
#define AS_LD 40    // halfs
#define WS_LD 136   // halfs

template <typename EPI>
__device__ __forceinline__ void gemm_core_f16(
    const float* __restrict__ A, const float* __restrict__ W,
    int K, int N, int m0, int n0, __half* As, __half* Ws, EPI epi)
{
    const int tid  = threadIdx.x;
    const int lane = tid & 31;
    const int w    = tid >> 5;
    const int gid  = lane >> 2;
    const int tig  = lane & 3;
    const int wm0  = (w & 1) * 64;
    const int wn0  = (w >> 1) * 32;
    const u32 ws_base = (u32)__cvta_generic_to_shared(Ws);
    const u32 as_base = (u32)__cvta_generic_to_shared(As);

    // ldmatrix source row for A-frags: matrix id = lane>>3
    const int a_id = lane >> 3;          // 0..3
    const int a_r  = lane & 7;
    const int a_row_off = (a_id & 1) * 8 + a_r;
    const int a_col_off = (a_id >> 1) * 8;

    float acc[4][4][4];
#pragma unroll
    for (int mt = 0; mt < 4; mt++)
#pragma unroll
        for (int nt = 0; nt < 4; nt++)
#pragma unroll
            for (int j = 0; j < 4; j++) acc[mt][nt][j] = 0.f;

    float4 ar[4], wrg[4];
#pragma unroll
    for (int p = 0; p < 4; p++) {
        int idx = tid + 256 * p;
        int row = idx >> 3, c4 = idx & 7;
        ar[p] = *reinterpret_cast<const float4*>(&A[(size_t)(m0 + row) * K + c4 * 4]);
        int kk = idx >> 5, wc4 = idx & 31;
        wrg[p] = *reinterpret_cast<const float4*>(&W[(size_t)kk * N + n0 + wc4 * 4]);
    }

    const int niter = K / 32;
    for (int kt = 0; kt < niter; kt++) {
        __syncthreads();
#pragma unroll
        for (int p = 0; p < 4; p++) {
            int idx = tid + 256 * p;
            int row = idx >> 3, c4 = idx & 7;
            *reinterpret_cast<uint2*>(&As[row * AS_LD + c4 * 4]) =
                make_uint2(pack_h2(ar[p].x, ar[p].y), pack_h2(ar[p].z, ar[p].w));
            int kk = idx >> 5, wc4 = idx & 31;
            *reinterpret_cast<uint2*>(&Ws[kk * WS_LD + wc4 * 4]) =
                make_uint2(pack_h2(wrg[p].x, wrg[p].y), pack_h2(wrg[p].z, wrg[p].w));
        }
        __syncthreads();

        if (kt + 1 < niter) {
            const int k0n = (kt + 1) * 32;
#pragma unroll
            for (int p = 0; p < 4; p++) {
                int idx = tid + 256 * p;
                int row = idx >> 3, c4 = idx & 7;
                ar[p] = *reinterpret_cast<const float4*>(
                    &A[(size_t)(m0 + row) * K + k0n + c4 * 4]);
                int kk = idx >> 5, wc4 = idx & 31;
                wrg[p] = *reinterpret_cast<const float4*>(
                    &W[(size_t)(k0n + kk) * N + n0 + wc4 * 4]);
            }
        }

#pragma unroll
        for (int ks = 0; ks < 2; ks++) {
            u32 af[4][4];
#pragma unroll
            for (int mt = 0; mt < 4; mt++) {
                u32 addr = as_base +
                    ((wm0 + mt * 16 + a_row_off) * AS_LD + ks * 16 + a_col_off) * 2;
                ldm_x4(af[mt][0], af[mt][1], af[mt][2], af[mt][3], addr);
            }
            u32 b0[4], b1[4];
#pragma unroll
            for (int nb = 0; nb < 2; nb++) {
                u32 addr = ws_base +
                    ((16 * ks + (lane & 15)) * WS_LD + wn0 + 16 * nb + (lane >> 4) * 8) * 2;
                ldm_x4t(b0[2 * nb], b1[2 * nb], b0[2 * nb + 1], b1[2 * nb + 1], addr);
            }
#pragma unroll
            for (int mt = 0; mt < 4; mt++)
#pragma unroll
                for (int nt = 0; nt < 4; nt++)
                    mma_f16(acc[mt][nt], af[mt], b0[nt], b1[nt]);
        }
    }
    epi(acc, wm0, wn0, gid, tig);
}

// ---------------- merged QKV projection (one launch, grid 9 x 64) -----------
__global__ __launch_bounds__(256, 2) void gemm_qkv_kernel(
    const float* __restrict__ x,
    const float* __restrict__ Wq, const float* __restrict__ bq,
    const float* __restrict__ Wk, const float* __restrict__ bk,
    const float* __restrict__ Wv, const float* __restrict__ bv,
    __half* __restrict__ qp, __half* __restrict__ kp, __half* __restrict__ vp)
{
    __shared__ __half As[128 * AS_LD];
    __shared__ __half Ws[32 * WS_LD];

    const int sel = blockIdx.x / 3;
    const int n0  = (blockIdx.x % 3) * 128;
    const int m0  = blockIdx.y * 128;
    const float* W    = (sel == 0) ? Wq : ((sel == 1) ? Wk : Wv);
    const float* bias = (sel == 0) ? bq : ((sel == 1) ? bk : bv);
    __half* out       = (sel == 0) ? qp : ((sel == 1) ? kp : vp);
    const float oscale = (sel == 0) ? QSCALE : 1.0f;

    gemm_core_f16(x, W, CDIM, CDIM, m0, n0, As, Ws,
        [&](float acc[4][4][4], int wm0, int wn0, int gid, int tig) {
#pragma unroll
            for (int mt = 0; mt < 4; mt++) {
#pragma unroll
                for (int half = 0; half < 2; half++) {
                    const int m = m0 + wm0 + mt * 16 + gid + half * 8;
#pragma unroll
                    for (int nt = 0; nt < 4; nt++) {
                        const int n = n0 + wn0 + nt * 8 + 2 * tig;
                        float vx = (acc[mt][nt][half * 2 + 0] + bias[n + 0]) * oscale;
                        float vy = (acc[mt][nt][half * 2 + 1] + bias[n + 1]) * oscale;
                        const int b = m >> 11, t = m & 2047;
                        const int h = n >> 6, d = n & 63;
                        *reinterpret_cast<u32*>(
                            &out[(((size_t)(b * HEADS + h) * T_SEQ + t) * DH) + d]) =
                            pack_h2(vx, vy);
                    }
                }
            }
        });
}

// ---------------- output projection: float out [M,N] ------------------------
__global__ __launch_bounds__(256, 2) void gemm_out_kernel(
    const float* __restrict__ A, const float* __restrict__ W,
    const float* __restrict__ bias, float* __restrict__ out)
{
    __shared__ __half As[128 * AS_LD];
    __shared__ __half Ws[32 * WS_LD];
    const int n0 = blockIdx.x * 128;
    const int m0 = blockIdx.y * 128;

    gemm_core_f16(A, W, CDIM, CDIM, m0, n0, As, Ws,
        [&](float acc[4][4][4], int wm0, int wn0, int gid, int tig) {
#pragma unroll
            for (int mt = 0; mt < 4; mt++) {
#pragma unroll
                for (int half = 0; half < 2; half++) {
                    const int m = m0 + wm0 + mt * 16 + gid + half * 8;
#pragma unroll
                    for (int nt = 0; nt < 4; nt++) {
                        const int n = n0 + wn0 + nt * 8 + 2 * tig;
                        *reinterpret_cast<float2*>(&out[(size_t)m * CDIM + n]) =
                            make_float2(acc[mt][nt][half * 2 + 0] + bias[n + 0],
                                        acc[mt][nt][half * 2 + 1] + bias[n + 1]);
                    }
                }
            }
        });
}

// ---------------- fp16 tensor-core causal flash attention -------------------
// BQ=128 (8 warps x 16 rows), BK=64, m16n8k16, P in registers, base-2 softmax,
// row-sums via P@ones mma, 3-stage cp.async ring (one barrier per tile).
#define BQ 128
#define BK 64
#define KS_LD 72   // halfs
#define VS_LD 72
#define STAGE_HALFS (BK * KS_LD + BK * VS_LD)       // 9216
#define ATTN_SMEM_BYTES (3 * STAGE_HALFS * 2)       // 55296

__global__ void __launch_bounds__(256, 2) attn_kernel(float* __restrict__ ctx)
{
    extern __shared__ __half smh[];

    const int tid  = threadIdx.x;
    const int lane = tid & 31;
    const int w    = tid >> 5;
    const int gid  = lane >> 2;
    const int tig  = lane & 3;

    const int bh = blockIdx.y;
    const int qi = gridDim.x - 1 - blockIdx.x;   // heavy blocks first
    const int q0 = qi * BQ;

    const __half* qb = g_q + (size_t)bh * T_SEQ * DH;
    const __half* kb = g_k + (size_t)bh * T_SEQ * DH;
    const __half* vb = g_v + (size_t)bh * T_SEQ * DH;

    // ---- Q A-frags straight from gmem (once per block) ----
    const int arow = w * 16 + gid;
    u32 qf[4][4];
#pragma unroll
    for (int s = 0; s < 4; s++) {
        const __half* base = &qb[(size_t)(q0 + arow) * DH + s * 16 + 2 * tig];
        qf[s][0] = *reinterpret_cast<const u32*>(base);
        qf[s][1] = *reinterpret_cast<const u32*>(base + 8 * DH);
        qf[s][2] = *reinterpret_cast<const u32*>(base + 8);
        qf[s][3] = *reinterpret_cast<const u32*>(base + 8 * DH + 8);
    }

    float O[8][4];
#pragma unroll
    for (int nt = 0; nt < 8; nt++)
#pragma unroll
        for (int j = 0; j < 4; j++) O[nt][j] = 0.f;
    float OS[4] = {0.f, 0.f, 0.f, 0.f};   // row-sum accumulator (l) via mma
    float mA = -1e30f, mB = -1e30f;

    const u32 smbase = (u32)__cvta_generic_to_shared(smh);
    u32 kbase[3], vbase[3];
#pragma unroll
    for (int s = 0; s < 3; s++) {
        kbase[s] = smbase + (s * STAGE_HALFS) * 2;
        vbase[s] = kbase[s] + (BK * KS_LD) * 2;
    }

    const int ldrow = tid >> 3;          // 0..31 base row (+32 for p=1)
    const int ldc   = tid & 7;           // 16B chunk within row (8 halfs)

    const int ntiles = 2 * qi + 2;

    // prologue: tiles 0 and 1 -> stages 0,1
#pragma unroll
    for (int st = 0; st < 2; st++) {
#pragma unroll
        for (int p = 0; p < 2; p++) {
            int row = ldrow + p * 32;
            cp_async16(kbase[st] + (row * KS_LD + ldc * 8) * 2,
                       &kb[(size_t)(st * BK + row) * DH + ldc * 8]);
            cp_async16(vbase[st] + (row * VS_LD + ldc * 8) * 2,
                       &vb[(size_t)(st * BK + row) * DH + ldc * 8]);
        }
        cp_commit();
    }

    for (int kt = 0; kt < ntiles; kt++) {
        const int k0 = kt * BK;
        if (kt + 2 <= ntiles) cp_wait1(); else cp_wait0();
        __syncthreads();

        // refill: stage (kt+2)%3 was fully consumed during iteration kt-1
        if (kt + 2 < ntiles) {
            const int kn = (kt + 2) * BK;
            const int st = (kt + 2) % 3;
#pragma unroll
            for (int p = 0; p < 2; p++) {
                int row = ldrow + p * 32;
                cp_async16(kbase[st] + (row * KS_LD + ldc * 8) * 2,
                           &kb[(size_t)(kn + row) * DH + ldc * 8]);
                cp_async16(vbase[st] + (row * VS_LD + ldc * 8) * 2,
                           &vb[(size_t)(kn + row) * DH + ldc * 8]);
            }
            cp_commit();
        }

        const int buf = kt % 3;

        if (k0 <= q0 + w * 16 + 15) {     // warp not entirely above diagonal
            // ---- S = Q K^T ----
            float S[8][4];
#pragma unroll
            for (int nt = 0; nt < 8; nt++)
#pragma unroll
                for (int j = 0; j < 4; j++) S[nt][j] = 0.f;
#pragma unroll
            for (int s = 0; s < 4; s++) {
#pragma unroll
                for (int p = 0; p < 4; p++) {
                    u32 r0, r1, r2, r3;
                    u32 addr = kbase[buf] +
                        (((16 * p + (lane & 15)) * KS_LD) + 16 * s + (lane >> 4) * 8) * 2;
                    ldm_x4(r0, r1, r2, r3, addr);
                    mma_f16(S[2 * p],     qf[s], r0, r2);
                    mma_f16(S[2 * p + 1], qf[s], r1, r3);
                }
            }

            // ---- causal mask ----
            const int rA = q0 + arow;
            const int rB = rA + 8;
            if (k0 + BK - 1 > rA) {
#pragma unroll
                for (int nt = 0; nt < 8; nt++) {
                    const int c0 = k0 + nt * 8 + 2 * tig;
                    if (c0     > rA) S[nt][0] = -1e30f;
                    if (c0 + 1 > rA) S[nt][1] = -1e30f;
                    if (c0     > rB) S[nt][2] = -1e30f;
                    if (c0 + 1 > rB) S[nt][3] = -1e30f;
                }
            }

            // ---- online softmax (base 2) ----
            float mxA = -1e30f, mxB = -1e30f;
#pragma unroll
            for (int nt = 0; nt < 8; nt++) {
                mxA = fmaxf(mxA, fmaxf(S[nt][0], S[nt][1]));
                mxB = fmaxf(mxB, fmaxf(S[nt][2], S[nt][3]));
            }
            mxA = fmaxf(mxA, __shfl_xor_sync(0xffffffffu, mxA, 1));
            mxA = fmaxf(mxA, __shfl_xor_sync(0xffffffffu, mxA, 2));
            mxB = fmaxf(mxB, __shfl_xor_sync(0xffffffffu, mxB, 1));
            mxB = fmaxf(mxB, __shfl_xor_sync(0xffffffffu, mxB, 2));

            const float mnA = fmaxf(mA, mxA), mnB = fmaxf(mB, mxB);
            const float aA = ex2f(mA - mnA), aB = ex2f(mB - mnB);
            mA = mnA;  mB = mnB;
#pragma unroll
            for (int nt = 0; nt < 8; nt++) {
                S[nt][0] = ex2f(S[nt][0] - mnA);
                S[nt][1] = ex2f(S[nt][1] - mnA);
                S[nt][2] = ex2f(S[nt][2] - mnB);
                S[nt][3] = ex2f(S[nt][3] - mnB);
            }
#pragma unroll
            for (int nt = 0; nt < 8; nt++) {
                O[nt][0] *= aA; O[nt][1] *= aA;
                O[nt][2] *= aB; O[nt][3] *= aB;
            }
            OS[0] *= aA; OS[1] *= aA; OS[2] *= aB; OS[3] *= aB;

            // ---- P: C-frag -> A-frag in registers ----
            u32 pa[4][4];
#pragma unroll
            for (int s2 = 0; s2 < 4; s2++) {
                pa[s2][0] = pack_h2(S[2 * s2][0],     S[2 * s2][1]);
                pa[s2][1] = pack_h2(S[2 * s2][2],     S[2 * s2][3]);
                pa[s2][2] = pack_h2(S[2 * s2 + 1][0], S[2 * s2 + 1][1]);
                pa[s2][3] = pack_h2(S[2 * s2 + 1][2], S[2 * s2 + 1][3]);
            }

            // ---- O += P V ; OS += P @ ones (row sums) ----
#pragma unroll
            for (int s2 = 0; s2 < 4; s2++) {
#pragma unroll
                for (int nb = 0; nb < 4; nb++) {
                    u32 r0, r1, r2, r3;
                    u32 addr = vbase[buf] +
                        (((16 * s2 + (lane & 15)) * VS_LD) + 16 * nb + (lane >> 4) * 8) * 2;
                    ldm_x4t(r0, r1, r2, r3, addr);
                    mma_f16(O[2 * nb],     pa[s2], r0, r1);
                    mma_f16(O[2 * nb + 1], pa[s2], r2, r3);
                }
                mma_f16(OS, pa[s2], ONES_H2, ONES_H2);
            }
        }
    }

    // ---- epilogue (l comes from the OS accumulator) ----
    const float iA = 1.f / OS[0], iB = 1.f / OS[2];
    const int b = bh / HEADS, h = bh % HEADS;
    const size_t rowA = (size_t)(b * T_SEQ + q0 + arow) * CDIM + h * DH;
    const size_t rowB = rowA + (size_t)8 * CDIM;
#pragma unroll
    for (int nt = 0; nt < 8; nt++) {
        *reinterpret_cast<float2*>(&ctx[rowA + nt * 8 + 2 * tig]) =
            make_float2(O[nt][0] * iA, O[nt][1] * iA);
        *reinterpret_cast<float2*>(&ctx[rowB + nt * 8 + 2 * tig]) =
            make_float2(O[nt][2] * iB, O[nt][3] * iB);
    }
}

// ---------------- launch ----------------------------------------------------
extern "C" void kernel_launch(void* const* d_in, const int* in_sizes, int n_in,
                              void* d_out, int out_size)
{
    (void)in_sizes; (void)n_in; (void)out_size;
    const float* x  = (const float*)d_in[0];
    const float* Wq = (const float*)d_in[1];
    const float* bq = (const float*)d_in[2];
    const float* Wk = (const float*)d_in[3];
    const float* bk = (const float*)d_in[4];
    const float* Wv = (const float*)d_in[5];
    const float* bv = (const float*)d_in[6];
    const float* Wo = (const float*)d_in[7];
    const float* bo = (const float*)d_in[8];
    float* out = (float*)d_out;

    static __half *qp = nullptr, *kp = nullptr, *vp = nullptr;
    static float* cp = nullptr;
    if (!qp) {
        cudaGetSymbolAddress((void**)&qp, g_q);
        cudaGetSymbolAddress((void**)&kp, g_k);
        cudaGetSymbolAddress((void**)&vp, g_v);
        cudaGetSymbolAddress((void**)&cp, g_ctx);
        cudaFuncSetAttribute(attn_kernel,
                             cudaFuncAttributeMaxDynamicSharedMemorySize,
                             ATTN_SMEM_BYTES);
    }

    dim3 gblk(256);

    // merged QKV projection: grid (9, 64)
    dim3 qkvgrid(9, MROWS / 128);
    gemm_qkv_kernel<<<qkvgrid, gblk>>>(x, Wq, bq, Wk, bk, Wv, bv, qp, kp, vp);

    dim3 agrid(T_SEQ / BQ, BATCH * HEADS);   // (16, 24)
    attn_kernel<<<agrid, 256, ATTN_SMEM_BYTES>>>(cp);

    dim3 ogrid(CDIM / 128, MROWS / 128);     // (3, 64)
    gemm_out_kernel<<<ogrid, gblk>>>(cp, Wo, bo, out);
}

// round 10
// speedup vs baseline: 18.4776x; 1.0343x over previous
#include <cuda_runtime.h>
#include <cuda_fp16.h>

// Problem constants
#define BATCH   4
#define T_SEQ   2048
#define CDIM    384
#define HEADS   6
#define DH      64
#define MROWS   (BATCH * T_SEQ)        // 8192

typedef unsigned int u32;

// Q pre-scale: 1/sqrt(64) * log2(e)  (base-2 softmax)
#define QSCALE (0.125f * 1.4426950408889634f)
#define ONES_H2 0x3C003C00u            // fp16 {1.0, 1.0}

// ---------------- scratch (static device globals; no runtime allocation) ----
__device__ __half g_xh[MROWS * CDIM];               // x in fp16
__device__ __half g_wh[4][CDIM * CDIM];             // Wq,Wk,Wv,Wo in fp16
__device__ __half g_q[BATCH * HEADS * T_SEQ * DH];  // [B,H,T,D], pre-scaled
__device__ __half g_k[BATCH * HEADS * T_SEQ * DH];
__device__ __half g_v[BATCH * HEADS * T_SEQ * DH];
__device__ __half g_ctx[MROWS * CDIM];              // [B*T, C] fp16

// ---------------- primitives ------------------------------------------------
__device__ __forceinline__ u32 pack_h2(float lo, float hi) {
    u32 r;
    asm("cvt.rn.f16x2.f32 %0, %1, %2;" : "=r"(r) : "f"(hi), "f"(lo));
    return r;
}
__device__ __forceinline__ float ex2f(float x) {
    float y;
    asm("ex2.approx.f32 %0, %1;" : "=f"(y) : "f"(x));
    return y;
}

__device__ __forceinline__ void mma_f16(float c[4], const u32 a[4], u32 b0, u32 b1) {
    asm volatile(
        "mma.sync.aligned.m16n8k16.row.col.f32.f16.f16.f32 "
        "{%0,%1,%2,%3}, {%4,%5,%6,%7}, {%8,%9}, {%0,%1,%2,%3};\n"
        : "+f"(c[0]), "+f"(c[1]), "+f"(c[2]), "+f"(c[3])
        : "r"(a[0]), "r"(a[1]), "r"(a[2]), "r"(a[3]), "r"(b0), "r"(b1));
}

__device__ __forceinline__ void ldm_x4(u32& r0, u32& r1, u32& r2, u32& r3, u32 addr) {
    asm volatile("ldmatrix.sync.aligned.m8n8.x4.shared.b16 {%0,%1,%2,%3}, [%4];"
                 : "=r"(r0), "=r"(r1), "=r"(r2), "=r"(r3) : "r"(addr));
}
__device__ __forceinline__ void ldm_x4t(u32& r0, u32& r1, u32& r2, u32& r3, u32 addr) {
    asm volatile("ldmatrix.sync.aligned.m8n8.x4.trans.shared.b16 {%0,%1,%2,%3}, [%4];"
                 : "=r"(r0), "=r"(r1), "=r"(r2), "=r"(r3) : "r"(addr));
}

__device__ __forceinline__ void cp_async16(u32 saddr, const void* gptr) {
    asm volatile("cp.async.cg.shared.global [%0], [%1], 16;" :: "r"(saddr), "l"(gptr));
}
__device__ __forceinline__ void cp_commit() { asm volatile("cp.async.commit_group;"); }
__device__ __forceinline__ void cp_wait1()  { asm volatile("cp.async.wait_group 1;"); }
__device__ __forceinline__ void cp_wait0()  { asm volatile("cp.async.wait_group 0;"); }

// ---------------- fp32 -> fp16 converters -----------------------------------
__global__ __launch_bounds__(256) void cvt_x_kernel(const float* __restrict__ in,
                                                    __half* __restrict__ out) {
    int i = (blockIdx.x * 256 + threadIdx.x) * 4;
    float4 v = *reinterpret_cast<const float4*>(in + i);
    *reinterpret_cast<uint2*>(out + i) =
        make_uint2(pack_h2(v.x, v.y), pack_h2(v.z, v.w));
}
__global__ __launch_bounds__(256) void cvt_w_kernel(
    const float* __restrict__ w0, const float* __restrict__ w1,
    const float* __restrict__ w2, const float* __restrict__ w3,
    __half* __restrict__ out) {
    const float* src = (blockIdx.y == 0) ? w0 : (blockIdx.y == 1) ? w1
                     : (blockIdx.y == 2) ? w2 : w3;
    int i = (blockIdx.x * 256 + threadIdx.x) * 4;
    float4 v = *reinterpret_cast<const float4*>(src + i);
    *reinterpret_cast<uint2*>(out + blockIdx.y * (CDIM * CDIM) + i) =
        make_uint2(pack_h2(v.x, v.y), pack_h2(v.z, v.w));
}

// ---------------- fp16 GEMM core: cp.async 3-stage, 128x128 tile, BK=32 -----
#define AS_LD 40    // halfs
#define WS_LD 136   // halfs
#define A_STAGE (128 * AS_LD)   // 5120 halfs
#define W_STAGE (32 * WS_LD)    // 4352 halfs
#define GEMM_SMEM_BYTES (3 * (A_STAGE + W_STAGE) * 2)   // 56832

template <typename EPI>
__device__ __forceinline__ void gemm_core_h(
    const __half* __restrict__ A, const __half* __restrict__ W,
    int K, int N, int m0, int n0, EPI epi)
{
    extern __shared__ __half sh[];
    __half* As = sh;
    __half* Ws = sh + 3 * A_STAGE;

    const int tid  = threadIdx.x;
    const int lane = tid & 31;
    const int w    = tid >> 5;
    const int gid  = lane >> 2;
    const int tig  = lane & 3;
    const int wm0  = (w & 1) * 64;
    const int wn0  = (w >> 1) * 32;
    const u32 as_base = (u32)__cvta_generic_to_shared(As);
    const u32 ws_base = (u32)__cvta_generic_to_shared(Ws);

    const int a_id = lane >> 3;
    const int a_r  = lane & 7;
    const int a_row_off = (a_id & 1) * 8 + a_r;
    const int a_col_off = (a_id >> 1) * 8;

    float acc[4][4][4];
#pragma unroll
    for (int mt = 0; mt < 4; mt++)
#pragma unroll
        for (int nt = 0; nt < 4; nt++)
#pragma unroll
            for (int j = 0; j < 4; j++) acc[mt][nt][j] = 0.f;

    auto issue = [&](int kt) {
        const int st = kt % 3;
        const __half* Ab = A + (size_t)m0 * K + kt * 32;
        const __half* Wb = W + (size_t)(kt * 32) * N + n0;
#pragma unroll
        for (int p = 0; p < 2; p++) {
            int id = tid + 256 * p;
            int arw = id >> 2, ac = id & 3;                 // A: 128 rows x 4 chunks
            cp_async16(as_base + (st * A_STAGE + arw * AS_LD + ac * 8) * 2,
                       Ab + (size_t)arw * K + ac * 8);
            int wrw = id >> 4, wc = id & 15;                // W: 32 rows x 16 chunks
            cp_async16(ws_base + (st * W_STAGE + wrw * WS_LD + wc * 8) * 2,
                       Wb + (size_t)wrw * N + wc * 8);
        }
        cp_commit();
    };

    issue(0);
    issue(1);

    const int niter = K / 32;
    for (int kt = 0; kt < niter; kt++) {
        if (kt + 2 <= niter) cp_wait1(); else cp_wait0();
        __syncthreads();
        if (kt + 2 < niter) issue(kt + 2);

        const int st = kt % 3;
        const u32 a_st = as_base + st * A_STAGE * 2;
        const u32 w_st = ws_base + st * W_STAGE * 2;

#pragma unroll
        for (int ks = 0; ks < 2; ks++) {
            u32 af[4][4];
#pragma unroll
            for (int mt = 0; mt < 4; mt++) {
                u32 addr = a_st +
                    ((wm0 + mt * 16 + a_row_off) * AS_LD + ks * 16 + a_col_off) * 2;
                ldm_x4(af[mt][0], af[mt][1], af[mt][2], af[mt][3], addr);
            }
            u32 b0[4], b1[4];
#pragma unroll
            for (int nb = 0; nb < 2; nb++) {
                u32 addr = w_st +
                    ((16 * ks + (lane & 15)) * WS_LD + wn0 + 16 * nb + (lane >> 4) * 8) * 2;
                ldm_x4t(b0[2 * nb], b1[2 * nb], b0[2 * nb + 1], b1[2 * nb + 1], addr);
            }
#pragma unroll
            for (int mt = 0; mt < 4; mt++)
#pragma unroll
                for (int nt = 0; nt < 4; nt++)
                    mma_f16(acc[mt][nt], af[mt], b0[nt], b1[nt]);
        }
    }
    epi(acc, wm0, wn0, gid, tig);
}

// ---------------- merged QKV projection (one launch, grid 9 x 64) -----------
__global__ __launch_bounds__(256, 2) void gemm_qkv_kernel(
    const float* __restrict__ bq, const float* __restrict__ bk,
    const float* __restrict__ bv,
    __half* __restrict__ qp, __half* __restrict__ kp, __half* __restrict__ vp)
{
    const int sel = blockIdx.x / 3;
    const int n0  = (blockIdx.x % 3) * 128;
    const int m0  = blockIdx.y * 128;
    const float* bias = (sel == 0) ? bq : ((sel == 1) ? bk : bv);
    __half* out       = (sel == 0) ? qp : ((sel == 1) ? kp : vp);
    const float oscale = (sel == 0) ? QSCALE : 1.0f;

    gemm_core_h(g_xh, g_wh[sel], CDIM, CDIM, m0, n0,
        [&](float acc[4][4][4], int wm0, int wn0, int gid, int tig) {
#pragma unroll
            for (int mt = 0; mt < 4; mt++) {
#pragma unroll
                for (int half = 0; half < 2; half++) {
                    const int m = m0 + wm0 + mt * 16 + gid + half * 8;
#pragma unroll
                    for (int nt = 0; nt < 4; nt++) {
                        const int n = n0 + wn0 + nt * 8 + 2 * tig;
                        float vx = (acc[mt][nt][half * 2 + 0] + bias[n + 0]) * oscale;
                        float vy = (acc[mt][nt][half * 2 + 1] + bias[n + 1]) * oscale;
                        const int b = m >> 11, t = m & 2047;
                        const int h = n >> 6, d = n & 63;
                        *reinterpret_cast<u32*>(
                            &out[(((size_t)(b * HEADS + h) * T_SEQ + t) * DH) + d]) =
                            pack_h2(vx, vy);
                    }
                }
            }
        });
}

// ---------------- output projection: A=ctx fp16, out float [M,N] ------------
__global__ __launch_bounds__(256, 2) void gemm_out_kernel(
    const float* __restrict__ bias, float* __restrict__ out)
{
    const int n0 = blockIdx.x * 128;
    const int m0 = blockIdx.y * 128;

    gemm_core_h(g_ctx, g_wh[3], CDIM, CDIM, m0, n0,
        [&](float acc[4][4][4], int wm0, int wn0, int gid, int tig) {
#pragma unroll
            for (int mt = 0; mt < 4; mt++) {
#pragma unroll
                for (int half = 0; half < 2; half++) {
                    const int m = m0 + wm0 + mt * 16 + gid + half * 8;
#pragma unroll
                    for (int nt = 0; nt < 4; nt++) {
                        const int n = n0 + wn0 + nt * 8 + 2 * tig;
                        *reinterpret_cast<float2*>(&out[(size_t)m * CDIM + n]) =
                            make_float2(acc[mt][nt][half * 2 + 0] + bias[n + 0],
                                        acc[mt][nt][half * 2 + 1] + bias[n + 1]);
                    }
                }
            }
        });
}

// ---------------- fp16 tensor-core causal flash attention -------------------
// BQ=128 (8 warps x 16 rows), BK=64, m16n8k16, P in registers, base-2 softmax,
// row-sums via P@ones mma, 3-stage cp.async ring, fp16 ctx output.
#define BQ 128
#define BK 64
#define KS_LD 72   // halfs
#define VS_LD 72
#define STAGE_HALFS (BK * KS_LD + BK * VS_LD)       // 9216
#define ATTN_SMEM_BYTES (3 * STAGE_HALFS * 2)       // 55296

__global__ void __launch_bounds__(256, 2) attn_kernel(__half* __restrict__ ctx)
{
    extern __shared__ __half smh[];

    const int tid  = threadIdx.x;
    const int lane = tid & 31;
    const int w    = tid >> 5;
    const int gid  = lane >> 2;
    const int tig  = lane & 3;

    const int bh = blockIdx.y;
    const int qi = gridDim.x - 1 - blockIdx.x;   // heavy blocks first
    const int q0 = qi * BQ;

    const __half* qb = g_q + (size_t)bh * T_SEQ * DH;
    const __half* kb = g_k + (size_t)bh * T_SEQ * DH;
    const __half* vb = g_v + (size_t)bh * T_SEQ * DH;

    // ---- Q A-frags straight from gmem (once per block) ----
    const int arow = w * 16 + gid;
    u32 qf[4][4];
#pragma unroll
    for (int s = 0; s < 4; s++) {
        const __half* base = &qb[(size_t)(q0 + arow) * DH + s * 16 + 2 * tig];
        qf[s][0] = *reinterpret_cast<const u32*>(base);
        qf[s][1] = *reinterpret_cast<const u32*>(base + 8 * DH);
        qf[s][2] = *reinterpret_cast<const u32*>(base + 8);
        qf[s][3] = *reinterpret_cast<const u32*>(base + 8 * DH + 8);
    }

    float O[8][4];
#pragma unroll
    for (int nt = 0; nt < 8; nt++)
#pragma unroll
        for (int j = 0; j < 4; j++) O[nt][j] = 0.f;
    float OS[4] = {0.f, 0.f, 0.f, 0.f};   // row-sum accumulator (l) via mma
    float mA = -1e30f, mB = -1e30f;

    const u32 smbase = (u32)__cvta_generic_to_shared(smh);
    u32 kbase[3], vbase[3];
#pragma unroll
    for (int s = 0; s < 3; s++) {
        kbase[s] = smbase + (s * STAGE_HALFS) * 2;
        vbase[s] = kbase[s] + (BK * KS_LD) * 2;
    }

    const int ldrow = tid >> 3;          // 0..31 base row (+32 for p=1)
    const int ldc   = tid & 7;           // 16B chunk within row (8 halfs)

    const int ntiles = 2 * qi + 2;

    // prologue: tiles 0 and 1 -> stages 0,1
#pragma unroll
    for (int st = 0; st < 2; st++) {
#pragma unroll
        for (int p = 0; p < 2; p++) {
            int row = ldrow + p * 32;
            cp_async16(kbase[st] + (row * KS_LD + ldc * 8) * 2,
                       &kb[(size_t)(st * BK + row) * DH + ldc * 8]);
            cp_async16(vbase[st] + (row * VS_LD + ldc * 8) * 2,
                       &vb[(size_t)(st * BK + row) * DH + ldc * 8]);
        }
        cp_commit();
    }

    for (int kt = 0; kt < ntiles; kt++) {
        const int k0 = kt * BK;
        if (kt + 2 <= ntiles) cp_wait1(); else cp_wait0();
        __syncthreads();

        if (kt + 2 < ntiles) {
            const int kn = (kt + 2) * BK;
            const int st = (kt + 2) % 3;
#pragma unroll
            for (int p = 0; p < 2; p++) {
                int row = ldrow + p * 32;
                cp_async16(kbase[st] + (row * KS_LD + ldc * 8) * 2,
                           &kb[(size_t)(kn + row) * DH + ldc * 8]);
                cp_async16(vbase[st] + (row * VS_LD + ldc * 8) * 2,
                           &vb[(size_t)(kn + row) * DH + ldc * 8]);
            }
            cp_commit();
        }

        const int buf = kt % 3;

        if (k0 <= q0 + w * 16 + 15) {
            // ---- S = Q K^T ----
            float S[8][4];
#pragma unroll
            for (int nt = 0; nt < 8; nt++)
#pragma unroll
                for (int j = 0; j < 4; j++) S[nt][j] = 0.f;
#pragma unroll
            for (int s = 0; s < 4; s++) {
#pragma unroll
                for (int p = 0; p < 4; p++) {
                    u32 r0, r1, r2, r3;
                    u32 addr = kbase[buf] +
                        (((16 * p + (lane & 15)) * KS_LD) + 16 * s + (lane >> 4) * 8) * 2;
                    ldm_x4(r0, r1, r2, r3, addr);
                    mma_f16(S[2 * p],     qf[s], r0, r2);
                    mma_f16(S[2 * p + 1], qf[s], r1, r3);
                }
            }

            // ---- causal mask ----
            const int rA = q0 + arow;
            const int rB = rA + 8;
            if (k0 + BK - 1 > rA) {
#pragma unroll
                for (int nt = 0; nt < 8; nt++) {
                    const int c0 = k0 + nt * 8 + 2 * tig;
                    if (c0     > rA) S[nt][0] = -1e30f;
                    if (c0 + 1 > rA) S[nt][1] = -1e30f;
                    if (c0     > rB) S[nt][2] = -1e30f;
                    if (c0 + 1 > rB) S[nt][3] = -1e30f;
                }
            }

            // ---- online softmax (base 2) ----
            float mxA = -1e30f, mxB = -1e30f;
#pragma unroll
            for (int nt = 0; nt < 8; nt++) {
                mxA = fmaxf(mxA, fmaxf(S[nt][0], S[nt][1]));
                mxB = fmaxf(mxB, fmaxf(S[nt][2], S[nt][3]));
            }
            mxA = fmaxf(mxA, __shfl_xor_sync(0xffffffffu, mxA, 1));
            mxA = fmaxf(mxA, __shfl_xor_sync(0xffffffffu, mxA, 2));
            mxB = fmaxf(mxB, __shfl_xor_sync(0xffffffffu, mxB, 1));
            mxB = fmaxf(mxB, __shfl_xor_sync(0xffffffffu, mxB, 2));

            const float mnA = fmaxf(mA, mxA), mnB = fmaxf(mB, mxB);
            const float aA = ex2f(mA - mnA), aB = ex2f(mB - mnB);
            mA = mnA;  mB = mnB;
#pragma unroll
            for (int nt = 0; nt < 8; nt++) {
                S[nt][0] = ex2f(S[nt][0] - mnA);
                S[nt][1] = ex2f(S[nt][1] - mnA);
                S[nt][2] = ex2f(S[nt][2] - mnB);
                S[nt][3] = ex2f(S[nt][3] - mnB);
            }
#pragma unroll
            for (int nt = 0; nt < 8; nt++) {
                O[nt][0] *= aA; O[nt][1] *= aA;
                O[nt][2] *= aB; O[nt][3] *= aB;
            }
            OS[0] *= aA; OS[1] *= aA; OS[2] *= aB; OS[3] *= aB;

            // ---- P: C-frag -> A-frag in registers ----
            u32 pa[4][4];
#pragma unroll
            for (int s2 = 0; s2 < 4; s2++) {
                pa[s2][0] = pack_h2(S[2 * s2][0],     S[2 * s2][1]);
                pa[s2][1] = pack_h2(S[2 * s2][2],     S[2 * s2][3]);
                pa[s2][2] = pack_h2(S[2 * s2 + 1][0], S[2 * s2 + 1][1]);
                pa[s2][3] = pack_h2(S[2 * s2 + 1][2], S[2 * s2 + 1][3]);
            }

            // ---- O += P V ; OS += P @ ones (row sums) ----
#pragma unroll
            for (int s2 = 0; s2 < 4; s2++) {
#pragma unroll
                for (int nb = 0; nb < 4; nb++) {
                    u32 r0, r1, r2, r3;
                    u32 addr = vbase[buf] +
                        (((16 * s2 + (lane & 15)) * VS_LD) + 16 * nb + (lane >> 4) * 8) * 2;
                    ldm_x4t(r0, r1, r2, r3, addr);
                    mma_f16(O[2 * nb],     pa[s2], r0, r1);
                    mma_f16(O[2 * nb + 1], pa[s2], r2, r3);
                }
                mma_f16(OS, pa[s2], ONES_H2, ONES_H2);
            }
        }
    }

    // ---- epilogue: fp16 ctx ----
    const float iA = 1.f / OS[0], iB = 1.f / OS[2];
    const int b = bh / HEADS, h = bh % HEADS;
    const size_t rowA = (size_t)(b * T_SEQ + q0 + arow) * CDIM + h * DH;
    const size_t rowB = rowA + (size_t)8 * CDIM;
#pragma unroll
    for (int nt = 0; nt < 8; nt++) {
        *reinterpret_cast<u32*>(&ctx[rowA + nt * 8 + 2 * tig]) =
            pack_h2(O[nt][0] * iA, O[nt][1] * iA);
        *reinterpret_cast<u32*>(&ctx[rowB + nt * 8 + 2 * tig]) =
            pack_h2(O[nt][2] * iB, O[nt][3] * iB);
    }
}

// ---------------- launch ----------------------------------------------------
extern "C" void kernel_launch(void* const* d_in, const int* in_sizes, int n_in,
                              void* d_out, int out_size)
{
    (void)in_sizes; (void)n_in; (void)out_size;
    const float* x  = (const float*)d_in[0];
    const float* Wq = (const float*)d_in[1];
    const float* bq = (const float*)d_in[2];
    const float* Wk = (const float*)d_in[3];
    const float* bk = (const float*)d_in[4];
    const float* Wv = (const float*)d_in[5];
    const float* bv = (const float*)d_in[6];
    const float* Wo = (const float*)d_in[7];
    const float* bo = (const float*)d_in[8];
    float* out = (float*)d_out;

    static __half *xh = nullptr, *wh = nullptr, *qp = nullptr, *kp = nullptr,
                  *vp = nullptr, *cp = nullptr;
    if (!xh) {
        cudaGetSymbolAddress((void**)&xh, g_xh);
        cudaGetSymbolAddress((void**)&wh, g_wh);
        cudaGetSymbolAddress((void**)&qp, g_q);
        cudaGetSymbolAddress((void**)&kp, g_k);
        cudaGetSymbolAddress((void**)&vp, g_v);
        cudaGetSymbolAddress((void**)&cp, g_ctx);
        cudaFuncSetAttribute(attn_kernel,
                             cudaFuncAttributeMaxDynamicSharedMemorySize,
                             ATTN_SMEM_BYTES);
        cudaFuncSetAttribute(gemm_qkv_kernel,
                             cudaFuncAttributeMaxDynamicSharedMemorySize,
                             GEMM_SMEM_BYTES);
        cudaFuncSetAttribute(gemm_out_kernel,
                             cudaFuncAttributeMaxDynamicSharedMemorySize,
                             GEMM_SMEM_BYTES);
    }

    // fp32 -> fp16 converts
    cvt_x_kernel<<<MROWS * CDIM / 1024, 256>>>(x, xh);
    dim3 wgrid(CDIM * CDIM / 1024, 4);
    cvt_w_kernel<<<wgrid, 256>>>(Wq, Wk, Wv, Wo, wh);

    // merged QKV projection: grid (9, 64)
    dim3 qkvgrid(9, MROWS / 128);
    gemm_qkv_kernel<<<qkvgrid, 256, GEMM_SMEM_BYTES>>>(bq, bk, bv, qp, kp, vp);

    dim3 agrid(T_SEQ / BQ, BATCH * HEADS);   // (16, 24)
    attn_kernel<<<agrid, 256, ATTN_SMEM_BYTES>>>(cp);

    dim3 ogrid(CDIM / 128, MROWS / 128);     // (3, 64)
    gemm_out_kernel<<<ogrid, 256, GEMM_SMEM_BYTES>>>(bo, out);
}

// round 12
// speedup vs baseline: 19.2140x; 1.0399x over previous
#include <cuda_runtime.h>
#include <cuda_fp16.h>

// Problem constants
#define BATCH   4
#define T_SEQ   2048
#define CDIM    384
#define HEADS   6
#define DH      64
#define MROWS   (BATCH * T_SEQ)        // 8192

typedef unsigned int u32;

// Q pre-scale: 1/sqrt(64) * log2(e)  (base-2 softmax)
#define QSCALE (0.125f * 1.4426950408889634f)
#define ONES_H2 0x3C003C00u            // fp16 {1.0, 1.0}

// ---------------- scratch (static device globals; no runtime allocation) ----
__device__ __half g_xh[MROWS * CDIM];               // x in fp16
__device__ __half g_wh[4][CDIM * CDIM];             // Wq,Wk,Wv,Wo in fp16
__device__ __half g_q[BATCH * HEADS * T_SEQ * DH];  // [B,H,T,D], pre-scaled
__device__ __half g_k[BATCH * HEADS * T_SEQ * DH];
__device__ __half g_v[BATCH * HEADS * T_SEQ * DH];
__device__ __half g_ctx[MROWS * CDIM];              // [B*T, C] fp16

// ---------------- primitives ------------------------------------------------
__device__ __forceinline__ u32 pack_h2(float lo, float hi) {
    u32 r;
    asm("cvt.rn.f16x2.f32 %0, %1, %2;" : "=r"(r) : "f"(hi), "f"(lo));
    return r;
}
__device__ __forceinline__ float ex2f(float x) {
    float y;
    asm("ex2.approx.f32 %0, %1;" : "=f"(y) : "f"(x));
    return y;
}
__device__ __forceinline__ u32 ex2h2(u32 x) {
    u32 y;
    asm("ex2.approx.f16x2 %0, %1;" : "=r"(y) : "r"(x));
    return y;
}

__device__ __forceinline__ void mma_f16(float c[4], const u32 a[4], u32 b0, u32 b1) {
    asm volatile(
        "mma.sync.aligned.m16n8k16.row.col.f32.f16.f16.f32 "
        "{%0,%1,%2,%3}, {%4,%5,%6,%7}, {%8,%9}, {%0,%1,%2,%3};\n"
        : "+f"(c[0]), "+f"(c[1]), "+f"(c[2]), "+f"(c[3])
        : "r"(a[0]), "r"(a[1]), "r"(a[2]), "r"(a[3]), "r"(b0), "r"(b1));
}

__device__ __forceinline__ void ldm_x4(u32& r0, u32& r1, u32& r2, u32& r3, u32 addr) {
    asm volatile("ldmatrix.sync.aligned.m8n8.x4.shared.b16 {%0,%1,%2,%3}, [%4];"
                 : "=r"(r0), "=r"(r1), "=r"(r2), "=r"(r3) : "r"(addr));
}
__device__ __forceinline__ void ldm_x4t(u32& r0, u32& r1, u32& r2, u32& r3, u32 addr) {
    asm volatile("ldmatrix.sync.aligned.m8n8.x4.trans.shared.b16 {%0,%1,%2,%3}, [%4];"
                 : "=r"(r0), "=r"(r1), "=r"(r2), "=r"(r3) : "r"(addr));
}

__device__ __forceinline__ void cp_async16(u32 saddr, const void* gptr) {
    asm volatile("cp.async.cg.shared.global [%0], [%1], 16;" :: "r"(saddr), "l"(gptr));
}
__device__ __forceinline__ void cp_commit() { asm volatile("cp.async.commit_group;"); }
__device__ __forceinline__ void cp_wait1()  { asm volatile("cp.async.wait_group 1;"); }
__device__ __forceinline__ void cp_wait0()  { asm volatile("cp.async.wait_group 0;"); }

// ---------------- fp32 -> fp16 converters -----------------------------------
__global__ __launch_bounds__(256) void cvt_x_kernel(const float* __restrict__ in,
                                                    __half* __restrict__ out) {
    int i = (blockIdx.x * 256 + threadIdx.x) * 4;
    float4 v = *reinterpret_cast<const float4*>(in + i);
    *reinterpret_cast<uint2*>(out + i) =
        make_uint2(pack_h2(v.x, v.y), pack_h2(v.z, v.w));
}
__global__ __launch_bounds__(256) void cvt_w_kernel(
    const float* __restrict__ w0, const float* __restrict__ w1,
    const float* __restrict__ w2, const float* __restrict__ w3,
    __half* __restrict__ out) {
    const float* src = (blockIdx.y == 0) ? w0 : (blockIdx.y == 1) ? w1
                     : (blockIdx.y == 2) ? w2 : w3;
    int i = (blockIdx.x * 256 + threadIdx.x) * 4;
    float4 v = *reinterpret_cast<const float4*>(src + i);
    *reinterpret_cast<uint2*>(out + blockIdx.y * (CDIM * CDIM) + i) =
        make_uint2(pack_h2(v.x, v.y), pack_h2(v.z, v.w));
}

// ---------------- fp16 GEMM core: cp.async 3-stage, 128x128 tile, BK=32 -----
#define AS_LD 40    // halfs
#define WS_LD 136   // halfs
#define A_STAGE (128 * AS_LD)   // 5120 halfs
#define W_STAGE (32 * WS_LD)    // 4352 halfs
#define GEMM_SMEM_BYTES (3 * (A_STAGE + W_STAGE) * 2)   // 56832

template <typename EPI>
__device__ __forceinline__ void gemm_core_h(
    const __half* __restrict__ A, const __half* __restrict__ W,
    int K, int N, int m0, int n0, EPI epi)
{
    extern __shared__ __half sh[];
    __half* As = sh;
    __half* Ws = sh + 3 * A_STAGE;

    const int tid  = threadIdx.x;
    const int lane = tid & 31;
    const int w    = tid >> 5;
    const int gid  = lane >> 2;
    const int tig  = lane & 3;
    const int wm0  = (w & 1) * 64;
    const int wn0  = (w >> 1) * 32;
    const u32 as_base = (u32)__cvta_generic_to_shared(As);
    const u32 ws_base = (u32)__cvta_generic_to_shared(Ws);

    const int a_id = lane >> 3;
    const int a_r  = lane & 7;
    const int a_row_off = (a_id & 1) * 8 + a_r;
    const int a_col_off = (a_id >> 1) * 8;

    float acc[4][4][4];
#pragma unroll
    for (int mt = 0; mt < 4; mt++)
#pragma unroll
        for (int nt = 0; nt < 4; nt++)
#pragma unroll
            for (int j = 0; j < 4; j++) acc[mt][nt][j] = 0.f;

    auto issue = [&](int kt) {
        const int st = kt % 3;
        const __half* Ab = A + (size_t)m0 * K + kt * 32;
        const __half* Wb = W + (size_t)(kt * 32) * N + n0;
#pragma unroll
        for (int p = 0; p < 2; p++) {
            int id = tid + 256 * p;
            int arw = id >> 2, ac = id & 3;
            cp_async16(as_base + (st * A_STAGE + arw * AS_LD + ac * 8) * 2,
                       Ab + (size_t)arw * K + ac * 8);
            int wrw = id >> 4, wc = id & 15;
            cp_async16(ws_base + (st * W_STAGE + wrw * WS_LD + wc * 8) * 2,
                       Wb + (size_t)wrw * N + wc * 8);
        }
        cp_commit();
    };

    issue(0);
    issue(1);

    const int niter = K / 32;
    for (int kt = 0; kt < niter; kt++) {
        if (kt + 2 <= niter) cp_wait1(); else cp_wait0();
        __syncthreads();
        if (kt + 2 < niter) issue(kt + 2);

        const int st = kt % 3;
        const u32 a_st = as_base + st * A_STAGE * 2;
        const u32 w_st = ws_base + st * W_STAGE * 2;

#pragma unroll
        for (int ks = 0; ks < 2; ks++) {
            u32 af[4][4];
#pragma unroll
            for (int mt = 0; mt < 4; mt++) {
                u32 addr = a_st +
                    ((wm0 + mt * 16 + a_row_off) * AS_LD + ks * 16 + a_col_off) * 2;
                ldm_x4(af[mt][0], af[mt][1], af[mt][2], af[mt][3], addr);
            }
            u32 b0[4], b1[4];
#pragma unroll
            for (int nb = 0; nb < 2; nb++) {
                u32 addr = w_st +
                    ((16 * ks + (lane & 15)) * WS_LD + wn0 + 16 * nb + (lane >> 4) * 8) * 2;
                ldm_x4t(b0[2 * nb], b1[2 * nb], b0[2 * nb + 1], b1[2 * nb + 1], addr);
            }
#pragma unroll
            for (int mt = 0; mt < 4; mt++)
#pragma unroll
                for (int nt = 0; nt < 4; nt++)
                    mma_f16(acc[mt][nt], af[mt], b0[nt], b1[nt]);
        }
    }
    epi(acc, wm0, wn0, gid, tig);
}

// ---------------- merged QKV projection (one launch, grid 9 x 64) -----------
__global__ __launch_bounds__(256, 2) void gemm_qkv_kernel(
    const float* __restrict__ bq, const float* __restrict__ bk,
    const float* __restrict__ bv,
    __half* __restrict__ qp, __half* __restrict__ kp, __half* __restrict__ vp)
{
    const int sel = blockIdx.x / 3;
    const int n0  = (blockIdx.x % 3) * 128;
    const int m0  = blockIdx.y * 128;
    const float* bias = (sel == 0) ? bq : ((sel == 1) ? bk : bv);
    __half* out       = (sel == 0) ? qp : ((sel == 1) ? kp : vp);
    const float oscale = (sel == 0) ? QSCALE : 1.0f;

    gemm_core_h(g_xh, g_wh[sel], CDIM, CDIM, m0, n0,
        [&](float acc[4][4][4], int wm0, int wn0, int gid, int tig) {
#pragma unroll
            for (int mt = 0; mt < 4; mt++) {
#pragma unroll
                for (int half = 0; half < 2; half++) {
                    const int m = m0 + wm0 + mt * 16 + gid + half * 8;
#pragma unroll
                    for (int nt = 0; nt < 4; nt++) {
                        const int n = n0 + wn0 + nt * 8 + 2 * tig;
                        float vx = (acc[mt][nt][half * 2 + 0] + bias[n + 0]) * oscale;
                        float vy = (acc[mt][nt][half * 2 + 1] + bias[n + 1]) * oscale;
                        const int b = m >> 11, t = m & 2047;
                        const int h = n >> 6, d = n & 63;
                        *reinterpret_cast<u32*>(
                            &out[(((size_t)(b * HEADS + h) * T_SEQ + t) * DH) + d]) =
                            pack_h2(vx, vy);
                    }
                }
            }
        });
}

// ---------------- output projection: A=ctx fp16, out float [M,N] ------------
__global__ __launch_bounds__(256, 2) void gemm_out_kernel(
    const float* __restrict__ bias, float* __restrict__ out)
{
    const int n0 = blockIdx.x * 128;
    const int m0 = blockIdx.y * 128;

    gemm_core_h(g_ctx, g_wh[3], CDIM, CDIM, m0, n0,
        [&](float acc[4][4][4], int wm0, int wn0, int gid, int tig) {
#pragma unroll
            for (int mt = 0; mt < 4; mt++) {
#pragma unroll
                for (int half = 0; half < 2; half++) {
                    const int m = m0 + wm0 + mt * 16 + gid + half * 8;
#pragma unroll
                    for (int nt = 0; nt < 4; nt++) {
                        const int n = n0 + wn0 + nt * 8 + 2 * tig;
                        *reinterpret_cast<float2*>(&out[(size_t)m * CDIM + n]) =
                            make_float2(acc[mt][nt][half * 2 + 0] + bias[n + 0],
                                        acc[mt][nt][half * 2 + 1] + bias[n + 1]);
                    }
                }
            }
        });
}

// ---------------- fp16 tensor-core causal flash attention -------------------
// BQ=128 (8 warps x 16 rows), 128-key softmax rounds (2 x 64-key mma passes),
// P in registers via ex2.approx.f16x2, row-sums via P@ones mma,
// 3-stage cp.async ring of 128-key stages, fp16 ctx output. occ 1 block/SM.
#define BQ 128
#define RK 128                        // keys per softmax round
#define KS_LD 72   // halfs
#define VS_LD 72
#define STAGE_HALFS (RK * KS_LD + RK * VS_LD)       // 18432
#define ATTN_SMEM_BYTES (3 * STAGE_HALFS * 2)       // 110592

__global__ void __launch_bounds__(256, 1) attn_kernel(__half* __restrict__ ctx)
{
    extern __shared__ __half smh[];

    const int tid  = threadIdx.x;
    const int lane = tid & 31;
    const int w    = tid >> 5;
    const int gid  = lane >> 2;
    const int tig  = lane & 3;

    const int bh = blockIdx.y;
    const int qi = gridDim.x - 1 - blockIdx.x;   // heavy blocks first
    const int q0 = qi * BQ;

    const __half* qb = g_q + (size_t)bh * T_SEQ * DH;
    const __half* kb = g_k + (size_t)bh * T_SEQ * DH;
    const __half* vb = g_v + (size_t)bh * T_SEQ * DH;

    // ---- Q A-frags straight from gmem (once per block) ----
    const int arow = w * 16 + gid;
    u32 qf[4][4];
#pragma unroll
    for (int s = 0; s < 4; s++) {
        const __half* base = &qb[(size_t)(q0 + arow) * DH + s * 16 + 2 * tig];
        qf[s][0] = *reinterpret_cast<const u32*>(base);
        qf[s][1] = *reinterpret_cast<const u32*>(base + 8 * DH);
        qf[s][2] = *reinterpret_cast<const u32*>(base + 8);
        qf[s][3] = *reinterpret_cast<const u32*>(base + 8 * DH + 8);
    }

    float O[8][4];
#pragma unroll
    for (int nt = 0; nt < 8; nt++)
#pragma unroll
        for (int j = 0; j < 4; j++) O[nt][j] = 0.f;
    float OS[4] = {0.f, 0.f, 0.f, 0.f};   // row-sum accumulator (l) via mma
    float mA = -1e30f, mB = -1e30f;

    const u32 smbase = (u32)__cvta_generic_to_shared(smh);
    u32 kbase[3], vbase[3];
#pragma unroll
    for (int s = 0; s < 3; s++) {
        kbase[s] = smbase + (s * STAGE_HALFS) * 2;
        vbase[s] = kbase[s] + (RK * KS_LD) * 2;
    }

    const int nrounds = qi + 1;

    // cp.async: 128 rows x 8 chunks per tensor per round; 4 K + 4 V per thread
    auto issue = [&](int r) {
        const int st = r % 3;
        const __half* kbr = kb + (size_t)(r * RK) * DH;
        const __half* vbr = vb + (size_t)(r * RK) * DH;
#pragma unroll
        for (int p = 0; p < 4; p++) {
            int id = tid + 256 * p;          // 0..1023
            int row = id >> 3, c = id & 7;   // 128 rows x 8 chunks
            cp_async16(kbase[st] + (row * KS_LD + c * 8) * 2,
                       kbr + (size_t)row * DH + c * 8);
            cp_async16(vbase[st] + (row * VS_LD + c * 8) * 2,
                       vbr + (size_t)row * DH + c * 8);
        }
        cp_commit();
    };

    issue(0);
    if (nrounds > 1) issue(1);

    for (int r = 0; r < nrounds; r++) {
        const int k0 = r * RK;
        if (r + 2 <= nrounds) cp_wait1(); else cp_wait0();
        __syncthreads();
        if (r + 2 < nrounds) issue(r + 2);

        const int buf = r % 3;

        // ---- S = Q K^T over 128 keys ----
        float S[16][4];
#pragma unroll
        for (int nt = 0; nt < 16; nt++)
#pragma unroll
            for (int j = 0; j < 4; j++) S[nt][j] = 0.f;
#pragma unroll
        for (int s = 0; s < 4; s++) {
#pragma unroll
            for (int p = 0; p < 8; p++) {
                u32 r0, r1, r2, r3;
                u32 addr = kbase[buf] +
                    (((16 * p + (lane & 15)) * KS_LD) + 16 * s + (lane >> 4) * 8) * 2;
                ldm_x4(r0, r1, r2, r3, addr);
                mma_f16(S[2 * p],     qf[s], r0, r2);
                mma_f16(S[2 * p + 1], qf[s], r1, r3);
            }
        }

        // ---- causal mask (only the diagonal round) ----
        const int rA = q0 + arow;
        const int rB = rA + 8;
        if (r == nrounds - 1) {
#pragma unroll
            for (int nt = 0; nt < 16; nt++) {
                const int c0 = k0 + nt * 8 + 2 * tig;
                if (c0     > rA) S[nt][0] = -1e30f;
                if (c0 + 1 > rA) S[nt][1] = -1e30f;
                if (c0     > rB) S[nt][2] = -1e30f;
                if (c0 + 1 > rB) S[nt][3] = -1e30f;
            }
        }

        // ---- online softmax (base 2), one round per 128 keys ----
        float mxA = -1e30f, mxB = -1e30f;
#pragma unroll
        for (int nt = 0; nt < 16; nt++) {
            mxA = fmaxf(mxA, fmaxf(S[nt][0], S[nt][1]));
            mxB = fmaxf(mxB, fmaxf(S[nt][2], S[nt][3]));
        }
        mxA = fmaxf(mxA, __shfl_xor_sync(0xffffffffu, mxA, 1));
        mxA = fmaxf(mxA, __shfl_xor_sync(0xffffffffu, mxA, 2));
        mxB = fmaxf(mxB, __shfl_xor_sync(0xffffffffu, mxB, 1));
        mxB = fmaxf(mxB, __shfl_xor_sync(0xffffffffu, mxB, 2));

        const float mnA = fmaxf(mA, mxA), mnB = fmaxf(mB, mxB);
        const float aA = ex2f(mA - mnA), aB = ex2f(mB - mnB);
        mA = mnA;  mB = mnB;
#pragma unroll
        for (int nt = 0; nt < 8; nt++) {
            O[nt][0] *= aA; O[nt][1] *= aA;
            O[nt][2] *= aB; O[nt][3] *= aB;
        }
        OS[0] *= aA; OS[1] *= aA; OS[2] *= aB; OS[3] *= aB;

        // ---- P = 2^(S - mn): pack f32 diffs, ex2 in f16x2 ----
        u32 pa[8][4];
#pragma unroll
        for (int s2 = 0; s2 < 8; s2++) {
            pa[s2][0] = ex2h2(pack_h2(S[2 * s2][0] - mnA, S[2 * s2][1] - mnA));
            pa[s2][1] = ex2h2(pack_h2(S[2 * s2][2] - mnB, S[2 * s2][3] - mnB));
            pa[s2][2] = ex2h2(pack_h2(S[2 * s2 + 1][0] - mnA, S[2 * s2 + 1][1] - mnA));
            pa[s2][3] = ex2h2(pack_h2(S[2 * s2 + 1][2] - mnB, S[2 * s2 + 1][3] - mnB));
        }

        // ---- O += P V ; OS += P @ ones (row sums) ----
#pragma unroll
        for (int s2 = 0; s2 < 8; s2++) {
#pragma unroll
            for (int nb = 0; nb < 4; nb++) {
                u32 r0, r1, r2, r3;
                u32 addr = vbase[buf] +
                    (((16 * s2 + (lane & 15)) * VS_LD) + 16 * nb + (lane >> 4) * 8) * 2;
                ldm_x4t(r0, r1, r2, r3, addr);
                mma_f16(O[2 * nb],     pa[s2], r0, r1);
                mma_f16(O[2 * nb + 1], pa[s2], r2, r3);
            }
            mma_f16(OS, pa[s2], ONES_H2, ONES_H2);
        }
    }

    // ---- epilogue: fp16 ctx ----
    const float iA = 1.f / OS[0], iB = 1.f / OS[2];
    const int b = bh / HEADS, h = bh % HEADS;
    const size_t rowA = (size_t)(b * T_SEQ + q0 + arow) * CDIM + h * DH;
    const size_t rowB = rowA + (size_t)8 * CDIM;
#pragma unroll
    for (int nt = 0; nt < 8; nt++) {
        *reinterpret_cast<u32*>(&ctx[rowA + nt * 8 + 2 * tig]) =
            pack_h2(O[nt][0] * iA, O[nt][1] * iA);
        *reinterpret_cast<u32*>(&ctx[rowB + nt * 8 + 2 * tig]) =
            pack_h2(O[nt][2] * iB, O[nt][3] * iB);
    }
}

// ---------------- launch ----------------------------------------------------
extern "C" void kernel_launch(void* const* d_in, const int* in_sizes, int n_in,
                              void* d_out, int out_size)
{
    (void)in_sizes; (void)n_in; (void)out_size;
    const float* x  = (const float*)d_in[0];
    const float* Wq = (const float*)d_in[1];
    const float* bq = (const float*)d_in[2];
    const float* Wk = (const float*)d_in[3];
    const float* bk = (const float*)d_in[4];
    const float* Wv = (const float*)d_in[5];
    const float* bv = (const float*)d_in[6];
    const float* Wo = (const float*)d_in[7];
    const float* bo = (const float*)d_in[8];
    float* out = (float*)d_out;

    static __half *xh = nullptr, *wh = nullptr, *qp = nullptr, *kp = nullptr,
                  *vp = nullptr, *cp = nullptr;
    if (!xh) {
        cudaGetSymbolAddress((void**)&xh, g_xh);
        cudaGetSymbolAddress((void**)&wh, g_wh);
        cudaGetSymbolAddress((void**)&qp, g_q);
        cudaGetSymbolAddress((void**)&kp, g_k);
        cudaGetSymbolAddress((void**)&vp, g_v);
        cudaGetSymbolAddress((void**)&cp, g_ctx);
        cudaFuncSetAttribute(attn_kernel,
                             cudaFuncAttributeMaxDynamicSharedMemorySize,
                             ATTN_SMEM_BYTES);
        cudaFuncSetAttribute(gemm_qkv_kernel,
                             cudaFuncAttributeMaxDynamicSharedMemorySize,
                             GEMM_SMEM_BYTES);
        cudaFuncSetAttribute(gemm_out_kernel,
                             cudaFuncAttributeMaxDynamicSharedMemorySize,
                             GEMM_SMEM_BYTES);
    }

    // fp32 -> fp16 converts
    cvt_x_kernel<<<MROWS * CDIM / 1024, 256>>>(x, xh);
    dim3 wgrid(CDIM * CDIM / 1024, 4);
    cvt_w_kernel<<<wgrid, 256>>>(Wq, Wk, Wv, Wo, wh);

    // merged QKV projection: grid (9, 64)
    dim3 qkvgrid(9, MROWS / 128);
    gemm_qkv_kernel<<<qkvgrid, 256, GEMM_SMEM_BYTES>>>(bq, bk, bv, qp, kp, vp);

    dim3 agrid(T_SEQ / BQ, BATCH * HEADS);   // (16, 24)
    attn_kernel<<<agrid, 256, ATTN_SMEM_BYTES>>>(cp);

    dim3 ogrid(CDIM / 128, MROWS / 128);     // (3, 64)
    gemm_out_kernel<<<ogrid, 256, GEMM_SMEM_BYTES>>>(bo, out);
}